// round 13
// baseline (speedup 1.0000x reference)
#include <cuda_runtime.h>
#include <cstdint>
#include <mma.h>
#include <math.h>

using namespace nvcuda;

#define BB 16      // batch
#define NR 512     // real points
#define NP 384     // padding points
#define NT 896     // total points per side
#define DD 256     // feature dim

// ---------------- scratch ----------------
__device__ float d_f1n[BB*NT*DD];       // normalized f1 (tf32-rounded)
__device__ float d_f2n[BB*NT*DD];       // normalized f2 (tf32-rounded)
__device__ float d_x3r[BB*NP*DD];       // tf32-rounded raw x3
__device__ float d_x4r[BB*NP*DD];       // tf32-rounded raw x4
__device__ float d_S  [BB*NR*NR];       // S then C (in-place)
__device__ float d_CT [BB*NR*NR];       // C transposed
__device__ float d_srp[BB*7*NT];
__device__ float d_scp[BB*7*NT];
__device__ float d_du0[BB*NR];          // f (cur 0)
__device__ float d_du1[BB*NR];          // g (cur 0)
__device__ float d_du2[BB*NR];          // f (cur 1) / final f
__device__ float d_du3[BB*NR];          // g (cur 1) / final g
__device__ float d_hpart[144];

// grid-barrier state (g_cnt returns to 0 after every barrier; g_gen monotonic)
__device__ unsigned int g_cnt;
__device__ unsigned int g_gen;

// ---------------- FMA-only helpers ----------------
// 2^y, clamped below at -125.  Degree-6 poly in r = y - round(y).
__device__ __forceinline__ float fexp2s(float y, float& scale) {
    y = fmaxf(y, -125.0f);
    float Y = y + 12582912.0f;           // round-to-nearest-int magic
    int   n = __float_as_int(Y);
    float fi = Y - 12582912.0f;
    float r = y - fi;                    // r in [-0.5, 0.5]
    float p =           1.5403530e-4f;   // (ln2)^6/720
    p = fmaf(p, r, 1.3333558e-3f);
    p = fmaf(p, r, 9.6181291e-3f);
    p = fmaf(p, r, 5.5504109e-2f);
    p = fmaf(p, r, 2.4022651e-1f);
    p = fmaf(p, r, 6.9314718e-1f);
    p = fmaf(p, r, 1.0f);
    scale = __int_as_float((unsigned)((n - 0x4B400000 + 127) << 23));
    return p;
}

__device__ __forceinline__ float fexp2v(float y) {
    float s;
    float p = fexp2s(y, s);
    return p * s;
}

__device__ __forceinline__ float frcp(float x) {
    float r = __int_as_float(0x7EF311C3 - __float_as_int(x));
    r = r * fmaf(-x, r, 2.0f);
    r = r * fmaf(-x, r, 2.0f);
    r = r * fmaf(-x, r, 2.0f);
    return r;
}

__device__ __forceinline__ void cp16(void* s, const void* g) {
    unsigned int sa = (unsigned int)__cvta_generic_to_shared(s);
    asm volatile("cp.async.cg.shared.global [%0], [%1], 16;" :: "r"(sa), "l"(g));
}

__device__ __forceinline__ float4 tf32x4(float4 v) {
    v.x = wmma::__float_to_tf32(v.x);
    v.y = wmma::__float_to_tf32(v.y);
    v.z = wmma::__float_to_tf32(v.z);
    v.w = wmma::__float_to_tf32(v.w);
    return v;
}

// software grid barrier (fence + atomics); all blocks must be co-resident
__device__ __forceinline__ void gridsync(int nb) {
    __threadfence();
    __syncthreads();
    if (threadIdx.x == 0) {
        unsigned int gen = atomicAdd(&g_gen, 0u);
        if (atomicAdd(&g_cnt, 1u) == (unsigned int)(nb - 1)) {
            atomicExch(&g_cnt, 0u);
            __threadfence();
            atomicAdd(&g_gen, 1u);
        } else {
            while (atomicAdd(&g_gen, 0u) == gen) { __nanosleep(64); }
        }
        __threadfence();
    }
    __syncthreads();
}

// ---------------- 1) normalize + tf32-round; also emit rounded raw x3/x4 ----------------
__global__ void __launch_bounds__(256) k_normalize(
    const float* __restrict__ x1, const float* __restrict__ x2,
    const float* __restrict__ x3, const float* __restrict__ x4)
{
    int gw   = blockIdx.x * 8 + (threadIdx.x >> 5);
    int lane = threadIdx.x & 31;
    int which = (gw >= BB*NT) ? 1 : 0;
    int r     = which ? gw - BB*NT : gw;
    int b = r / NT, i = r % NT;
    const float* src;
    float* rawdst = nullptr;
    if (i < NR) {
        src = (which ? x2 : x1) + ((size_t)(b*NR + i)) * DD;
    } else {
        size_t off = ((size_t)(b*NP + (i - NR))) * DD;
        src = (which ? x4 : x3) + off;
        rawdst = (which ? d_x4r : d_x3r) + off;
    }
    float* dst = (which ? d_f2n : d_f1n) + (size_t)r * DD;

    float4 v0 = *(const float4*)(src + lane*4);
    float4 v1 = *(const float4*)(src + 128 + lane*4);
    if (rawdst) {
        *(float4*)(rawdst + lane*4)       = tf32x4(v0);
        *(float4*)(rawdst + 128 + lane*4) = tf32x4(v1);
    }
    float sq = v0.x*v0.x + v0.y*v0.y + v0.z*v0.z + v0.w*v0.w
             + v1.x*v1.x + v1.y*v1.y + v1.z*v1.z + v1.w*v1.w;
    #pragma unroll
    for (int o = 16; o; o >>= 1) sq += __shfl_xor_sync(0xffffffffu, sq, o);
    float rn = 1.0f / fmaxf(sqrtf(sq), 1e-12f);
    v0.x *= rn; v0.y *= rn; v0.z *= rn; v0.w *= rn;
    v1.x *= rn; v1.y *= rn; v1.z *= rn; v1.w *= rn;
    *(float4*)(dst + lane*4)       = tf32x4(v0);
    *(float4*)(dst + 128 + lane*4) = tf32x4(v1);
}

// ---------------- 2) pipelined tf32 GEMM, 4 warps x (64x64); hinge folded into pad x pad blocks ----------------
#define LDA 36                // ≡4 mod 32 -> conflict-free fragment loads
#define LDE 132
#define STAGE (128*LDA)       // 4608 floats
#define SIM_SMEM (4*STAGE*4)  // 73728 bytes (>= 128*LDE*4 = 67584 for epilogue)
#define L2E10 14.4269504088896340736f   // 10 * log2(e)

__global__ void __launch_bounds__(128) k_simgemm()
{
    extern __shared__ float sh[];

    int b  = blockIdx.z;
    int m0 = blockIdx.y * 128, n0 = blockIdx.x * 128;
    bool hingeblk = (m0 >= NR) && (n0 >= NR);   // 3x3 pad x pad region -> hinge tiles

    const float *Ag, *Bg;
    if (hingeblk) {
        int hm = m0 - NR, hn = n0 - NR;          // 0,128,256 over NP=384
        Ag = d_x3r + (size_t)b * NP * DD + (size_t)hm * DD;
        Bg = d_x4r + (size_t)b * NP * DD + (size_t)hn * DD;
    } else {
        Ag = d_f1n + (size_t)b * NT * DD + (size_t)m0 * DD;
        Bg = d_f2n + (size_t)b * NT * DD + (size_t)n0 * DD;
    }

    int tid = threadIdx.x;              // 128 threads, 4 warps
    int wid = tid >> 5;
    int lane = tid & 31;
    int warp_m = wid >> 1;              // 0..1
    int warp_n = wid & 1;               // 0..1

    wmma::fragment<wmma::accumulator,16,16,8,float> acc[4][4];
    #pragma unroll
    for (int mt = 0; mt < 4; mt++)
        #pragma unroll
        for (int nt = 0; nt < 4; nt++)
            wmma::fill_fragment(acc[mt][nt], 0.0f);

    int lrow = tid >> 3;                // 0..15
    int lc4  = (tid & 7) * 4;

    {
        float* A = sh; float* B = sh + STAGE;
        #pragma unroll
        for (int u = 0; u < 8; u++) {
            int row = lrow + 16*u;
            cp16(&A[row*LDA + lc4], Ag + (size_t)row*DD + lc4);
            cp16(&B[row*LDA + lc4], Bg + (size_t)row*DD + lc4);
        }
        asm volatile("cp.async.commit_group;");
    }

    for (int kc = 0; kc < 8; kc++) {
        if (kc < 7) {
            float* A = sh + ((kc+1)&1)*2*STAGE;
            float* B = A + STAGE;
            int k0 = (kc+1)*32;
            #pragma unroll
            for (int u = 0; u < 8; u++) {
                int row = lrow + 16*u;
                cp16(&A[row*LDA + lc4], Ag + (size_t)row*DD + k0 + lc4);
                cp16(&B[row*LDA + lc4], Bg + (size_t)row*DD + k0 + lc4);
            }
            asm volatile("cp.async.commit_group;");
            asm volatile("cp.async.wait_group 1;");
        } else {
            asm volatile("cp.async.wait_group 0;");
        }
        __syncthreads();
        const float* A = sh + (kc&1)*2*STAGE;
        const float* B = A + STAGE;
        #pragma unroll
        for (int ks = 0; ks < 4; ks++) {
            wmma::fragment<wmma::matrix_a,16,16,8,wmma::precision::tf32,wmma::row_major> af[4];
            wmma::fragment<wmma::matrix_b,16,16,8,wmma::precision::tf32,wmma::col_major> bf[4];
            #pragma unroll
            for (int mt = 0; mt < 4; mt++)
                wmma::load_matrix_sync(af[mt], &A[(warp_m*64 + mt*16)*LDA + ks*8], LDA);
            #pragma unroll
            for (int nt = 0; nt < 4; nt++)
                wmma::load_matrix_sync(bf[nt], &B[(warp_n*64 + nt*16)*LDA + ks*8], LDA);
            #pragma unroll
            for (int mt = 0; mt < 4; mt++)
                #pragma unroll
                for (int nt = 0; nt < 4; nt++)
                    wmma::mma_sync(acc[mt][nt], af[mt], bf[nt], acc[mt][nt]);
        }
        __syncthreads();
    }

    if (hingeblk) {
        // hinge epilogue: sum relu(0.1 - v) over fragments (deterministic order)
        float loc = 0.f;
        #pragma unroll
        for (int mt = 0; mt < 4; mt++)
            #pragma unroll
            for (int nt = 0; nt < 4; nt++)
                #pragma unroll
                for (int e = 0; e < acc[mt][nt].num_elements; e++)
                    loc += fmaxf(0.1f - acc[mt][nt].x[e], 0.0f);
        __shared__ float red[4];
        #pragma unroll
        for (int o = 16; o; o >>= 1) loc += __shfl_xor_sync(0xffffffffu, loc, o);
        if (lane == 0) red[wid] = loc;
        __syncthreads();
        if (tid == 0)
            d_hpart[b*9 + (blockIdx.y - 4)*3 + (blockIdx.x - 4)] =
                (red[0] + red[1]) + (red[2] + red[3]);
        return;
    }

    // sim epilogue: store acc to sh[128][LDE], thread-per-row exp + sums
    #pragma unroll
    for (int mt = 0; mt < 4; mt++)
        #pragma unroll
        for (int nt = 0; nt < 4; nt++)
            wmma::store_matrix_sync(&sh[(warp_m*64 + mt*16)*LDE + warp_n*64 + nt*16],
                                    acc[mt][nt], LDE, wmma::mem_row_major);
    __syncthreads();

    bool inblk = (m0 < NR) && (n0 < NR);
    int ig = m0 + tid;
    float rsum = 0.f;
    float* Srow = d_S + ((size_t)b*NR + ig)*NR + n0;
    #pragma unroll
    for (int q = 0; q < 32; q++) {
        float4 v4 = *(float4*)&sh[tid*LDE + q*4];
        v4.x = fexp2v(L2E10 * v4.x);
        v4.y = fexp2v(L2E10 * v4.y);
        v4.z = fexp2v(L2E10 * v4.z);
        v4.w = fexp2v(L2E10 * v4.w);
        rsum += (v4.x + v4.y) + (v4.z + v4.w);
        *(float4*)&sh[tid*LDE + q*4] = v4;
        if (inblk) *(float4*)(Srow + q*4) = v4;
    }
    d_srp[((size_t)b*7 + (n0 >> 7))*NT + ig] = rsum;
    __syncthreads();

    float cs = 0.f;
    #pragma unroll 8
    for (int r = 0; r < 128; r++) cs += sh[r*LDE + tid];
    d_scp[((size_t)b*7 + (m0 >> 7))*NT + n0 + tid] = cs;
}

// ---------------- 3) cost (with fused partial-sum reduction): C = 1 - s/(sc+sr-s) + C^T ----------------
__global__ void k_cost()
{
    int b  = blockIdx.z;
    int j0 = blockIdx.x * 32, i0 = blockIdx.y * 32;
    float* S  = d_S  + (size_t)b * NR * NR;
    float* CT = d_CT + (size_t)b * NR * NR;
    __shared__ float tile[32][33];
    __shared__ float srv[32];
    __shared__ float scv[32];
    int tx = threadIdx.x, ty = threadIdx.y;   // (32, 8)
    int tid = ty*32 + tx;

    if (tid < 64) {
        int which = tid >> 5;    // 0: col sums, 1: row sums
        int idx   = tid & 31;
        const float* P = which ? (d_srp + (size_t)b*7*NT + i0 + idx)
                               : (d_scp + (size_t)b*7*NT + j0 + idx);
        float s = 0.f;
        #pragma unroll
        for (int t = 0; t < 7; t++) s += P[(size_t)t*NT];
        (which ? srv : scv)[idx] = s;
    }
    __syncthreads();

    int j = j0 + tx;
    float sc_j = scv[tx];
    #pragma unroll
    for (int r = 0; r < 4; r++) {
        int i = i0 + ty + 8*r;
        float s   = S[(size_t)i * NR + j];
        float den = sc_j + srv[ty + 8*r] - s;
        float c   = fmaf(-s, frcp(den), 1.0f);
        S[(size_t)i * NR + j] = c;
        tile[ty + 8*r][tx] = c;
    }
    __syncthreads();
    #pragma unroll
    for (int r = 0; r < 4; r++) {
        int ii = j0 + ty + 8*r;
        int jj = i0 + tx;
        CT[(size_t)ii * NR + jj] = tile[tx][ty + 8*r];
    }
}

// ---------------- 4) persistent softmin: 10 passes + finalize, grid 1024 co-resident ----------------
#define SGRID 1024

__global__ void __launch_bounds__(256, 7) k_softmin_all(float* __restrict__ out)
{
    int tid   = threadIdx.x;
    int lane  = tid & 31;
    int warp0 = blockIdx.x * 8 + (tid >> 5);
    int nb    = gridDim.x;
    int stride = nb * 8;

    const float EPSA[8] = {9.0f, 9.0f, 2.25f, 0.5625f, 0.140625f,
                           0.03515625f, 0.0087890625f, 0.0025f};
    const float L2E = 1.4426950408889634f;

    float* FB[2] = {d_du0, d_du2};
    float* GB[2] = {d_du1, d_du3};
    int cur = 0;

    for (int p = 0; p < 10; p++) {
        float eps, keps;
        const float *hf, *hg, *of, *og;
        float *wf, *wg;
        int avg;
        if (p == 0) {
            eps = 9.0f; keps = L2E / 9.0f;
            hf = hg = of = og = nullptr;
            wf = FB[0]; wg = GB[0]; avg = 0;
        } else if (p < 9) {
            eps = EPSA[p-1]; keps = L2E / eps;
            hf = GB[cur]; hg = FB[cur];
            of = FB[cur]; og = GB[cur];
            wf = FB[cur^1]; wg = GB[cur^1]; avg = 1;
        } else {
            eps = 0.0025f; keps = L2E / 0.0025f;
            hf = GB[cur]; hg = FB[cur];
            of = og = nullptr;
            wf = FB[cur^1]; wg = GB[cur^1]; avg = 0;   // cur==0 here -> du2/du3
        }

        for (int gw = warp0; gw < 2*BB*NR; gw += stride) {
            int side = (gw >= BB*NR) ? 1 : 0;
            int row  = side ? gw - BB*NR : gw;
            int b    = row >> 9;
            const float* Crow = (side ? d_CT : d_S) + (size_t)row * NR;
            const float* hv   = side ? hg : hf;
            const float* hb   = hv ? hv + (b << 9) : nullptr;

            float a[16];
            #pragma unroll
            for (int q = 0; q < 4; q++) {
                int j = q*128 + lane*4;
                float4 c4 = *(const float4*)(Crow + j);
                if (hb) {
                    float4 h4 = *(const float4*)(hb + j);
                    a[q*4+0] = (h4.x - c4.x) * keps;
                    a[q*4+1] = (h4.y - c4.y) * keps;
                    a[q*4+2] = (h4.z - c4.z) * keps;
                    a[q*4+3] = (h4.w - c4.w) * keps;
                } else {
                    a[q*4+0] = -c4.x * keps;
                    a[q*4+1] = -c4.y * keps;
                    a[q*4+2] = -c4.z * keps;
                    a[q*4+3] = -c4.w * keps;
                }
            }
            float m = a[0];
            #pragma unroll
            for (int u = 1; u < 16; u++) m = fmaxf(m, a[u]);
            #pragma unroll
            for (int o = 16; o; o >>= 1) m = fmaxf(m, __shfl_xor_sync(0xffffffffu, m, o));

            float s0 = 0.f, s1 = 0.f;
            #pragma unroll
            for (int u = 0; u < 8; u++) {
                float sc0, sc1;
                float p0 = fexp2s(a[2*u]   - m, sc0);
                float p1 = fexp2s(a[2*u+1] - m, sc1);
                s0 = fmaf(p0, sc0, s0);
                s1 = fmaf(p1, sc1, s1);
            }
            float s = s0 + s1;
            #pragma unroll
            for (int o = 16; o; o >>= 1) s += __shfl_xor_sync(0xffffffffu, s, o);
            if (lane == 0) {
                float val = -eps * (fmaf(m, 0.69314718055994531f, logf(s)));
                if (avg) val = 0.5f * ((side ? og : of)[row] + val);
                (side ? wg : wf)[row] = val;
            }
        }
        if (p > 0 && p < 9) cur ^= 1;
        gridsync(nb);
    }

    // finalize (block 0): deterministic double reduction
    if (blockIdx.x == 0) {
        __shared__ double sa[256];
        __shared__ double sb[256];
        double acc = 0.0;
        for (int idx = tid; idx < BB*NR; idx += 256)
            acc += (double)d_du2[idx] + (double)d_du3[idx];
        double h = 0.0;
        for (int idx = tid; idx < 144; idx += 256) h += (double)d_hpart[idx];
        sa[tid] = acc; sb[tid] = h;
        __syncthreads();
        for (int o = 128; o; o >>= 1) {
            if (tid < o) { sa[tid] += sa[tid + o]; sb[tid] += sb[tid + o]; }
            __syncthreads();
        }
        if (tid == 0) {
            out[0] = (float)sb[0];
            out[1] = (float)(sa[0] / (double)BB);
        }
    }
}

// ---------------- host ----------------
extern "C" void kernel_launch(void* const* d_in, const int* in_sizes, int n_in,
                              void* d_out, int out_size)
{
    const float* x1 = (const float*)d_in[0];
    const float* x2 = (const float*)d_in[1];
    const float* x3 = (const float*)d_in[2];
    const float* x4 = (const float*)d_in[3];
    float* out = (float*)d_out;

    cudaFuncSetAttribute(k_simgemm, cudaFuncAttributeMaxDynamicSharedMemorySize, SIM_SMEM);

    k_normalize<<<2*BB*NT/8, 256>>>(x1, x2, x3, x4);
    k_simgemm<<<dim3(7, 7, BB), 128, SIM_SMEM>>>();
    k_cost<<<dim3(NR/32, NR/32, BB), dim3(32, 8)>>>();
    k_softmin_all<<<SGRID, 256>>>(out);
}

// round 14
// speedup vs baseline: 1.2758x; 1.2758x over previous
#include <cuda_runtime.h>
#include <cstdint>
#include <mma.h>
#include <math.h>

using namespace nvcuda;

#define BB 16      // batch
#define NR 512     // real points
#define NP 384     // padding points
#define NT 896     // total points per side
#define DD 256     // feature dim

// ---------------- scratch ----------------
__device__ float d_f1n[BB*NT*DD];       // normalized f1 (tf32-rounded)
__device__ float d_f2n[BB*NT*DD];       // normalized f2 (tf32-rounded)
__device__ float d_x3r[BB*NP*DD];       // tf32-rounded raw x3
__device__ float d_x4r[BB*NP*DD];       // tf32-rounded raw x4
__device__ float d_S  [BB*NR*NR];       // S then C (in-place)
__device__ float d_CT [BB*NR*NR];       // C transposed
__device__ float d_srp[BB*7*NT];
__device__ float d_scp[BB*7*NT];
__device__ float d_du0[BB*NR];
__device__ float d_du1[BB*NR];
__device__ float d_du2[BB*NR];
__device__ float d_du3[BB*NR];
__device__ float d_hpart[144];

// ---------------- FMA-only helpers ----------------
// 2^y, clamped below at -125.  Degree-6 poly in r = y - round(y).
__device__ __forceinline__ float fexp2s(float y, float& scale) {
    y = fmaxf(y, -125.0f);
    float Y = y + 12582912.0f;           // round-to-nearest-int magic
    int   n = __float_as_int(Y);
    float fi = Y - 12582912.0f;
    float r = y - fi;                    // r in [-0.5, 0.5]
    float p =           1.5403530e-4f;   // (ln2)^6/720
    p = fmaf(p, r, 1.3333558e-3f);
    p = fmaf(p, r, 9.6181291e-3f);
    p = fmaf(p, r, 5.5504109e-2f);
    p = fmaf(p, r, 2.4022651e-1f);
    p = fmaf(p, r, 6.9314718e-1f);
    p = fmaf(p, r, 1.0f);
    scale = __int_as_float((unsigned)((n - 0x4B400000 + 127) << 23));
    return p;
}

__device__ __forceinline__ float fexp2v(float y) {
    float s;
    float p = fexp2s(y, s);
    return p * s;
}

__device__ __forceinline__ float frcp(float x) {
    float r = __int_as_float(0x7EF311C3 - __float_as_int(x));
    r = r * fmaf(-x, r, 2.0f);
    r = r * fmaf(-x, r, 2.0f);
    r = r * fmaf(-x, r, 2.0f);
    return r;
}

__device__ __forceinline__ void cp16(void* s, const void* g) {
    unsigned int sa = (unsigned int)__cvta_generic_to_shared(s);
    asm volatile("cp.async.cg.shared.global [%0], [%1], 16;" :: "r"(sa), "l"(g));
}

__device__ __forceinline__ float4 tf32x4(float4 v) {
    v.x = wmma::__float_to_tf32(v.x);
    v.y = wmma::__float_to_tf32(v.y);
    v.z = wmma::__float_to_tf32(v.z);
    v.w = wmma::__float_to_tf32(v.w);
    return v;
}

// ---------------- 1) normalize + tf32-round; also emit rounded raw x3/x4 ----------------
__global__ void __launch_bounds__(256) k_normalize(
    const float* __restrict__ x1, const float* __restrict__ x2,
    const float* __restrict__ x3, const float* __restrict__ x4)
{
    int gw   = blockIdx.x * 8 + (threadIdx.x >> 5);
    int lane = threadIdx.x & 31;
    int which = (gw >= BB*NT) ? 1 : 0;
    int r     = which ? gw - BB*NT : gw;
    int b = r / NT, i = r % NT;
    const float* src;
    float* rawdst = nullptr;
    if (i < NR) {
        src = (which ? x2 : x1) + ((size_t)(b*NR + i)) * DD;
    } else {
        size_t off = ((size_t)(b*NP + (i - NR))) * DD;
        src = (which ? x4 : x3) + off;
        rawdst = (which ? d_x4r : d_x3r) + off;
    }
    float* dst = (which ? d_f2n : d_f1n) + (size_t)r * DD;

    float4 v0 = *(const float4*)(src + lane*4);
    float4 v1 = *(const float4*)(src + 128 + lane*4);
    if (rawdst) {
        *(float4*)(rawdst + lane*4)       = tf32x4(v0);
        *(float4*)(rawdst + 128 + lane*4) = tf32x4(v1);
    }
    float sq = v0.x*v0.x + v0.y*v0.y + v0.z*v0.z + v0.w*v0.w
             + v1.x*v1.x + v1.y*v1.y + v1.z*v1.z + v1.w*v1.w;
    #pragma unroll
    for (int o = 16; o; o >>= 1) sq += __shfl_xor_sync(0xffffffffu, sq, o);
    float rn = 1.0f / fmaxf(sqrtf(sq), 1e-12f);
    v0.x *= rn; v0.y *= rn; v0.z *= rn; v0.w *= rn;
    v1.x *= rn; v1.y *= rn; v1.z *= rn; v1.w *= rn;
    *(float4*)(dst + lane*4)       = tf32x4(v0);
    *(float4*)(dst + 128 + lane*4) = tf32x4(v1);
}

// ---------------- 2) pipelined tf32 GEMM, 4 warps x (64x64); hinge folded into pad x pad blocks ----------------
#define LDA 36                // ≡4 mod 32 -> conflict-free fragment loads
#define LDE 132
#define STAGE (128*LDA)       // 4608 floats
#define SIM_SMEM (4*STAGE*4)  // 73728 bytes (>= 128*LDE*4 = 67584 for epilogue)
#define L2E10 14.4269504088896340736f   // 10 * log2(e)

__global__ void __launch_bounds__(128) k_simgemm()
{
    extern __shared__ float sh[];

    int b  = blockIdx.z;
    int m0 = blockIdx.y * 128, n0 = blockIdx.x * 128;
    bool hingeblk = (m0 >= NR) && (n0 >= NR);   // 3x3 pad x pad region -> hinge tiles

    const float *Ag, *Bg;
    if (hingeblk) {
        int hm = m0 - NR, hn = n0 - NR;          // 0,128,256 over NP=384
        Ag = d_x3r + (size_t)b * NP * DD + (size_t)hm * DD;
        Bg = d_x4r + (size_t)b * NP * DD + (size_t)hn * DD;
    } else {
        Ag = d_f1n + (size_t)b * NT * DD + (size_t)m0 * DD;
        Bg = d_f2n + (size_t)b * NT * DD + (size_t)n0 * DD;
    }

    int tid = threadIdx.x;              // 128 threads, 4 warps
    int wid = tid >> 5;
    int lane = tid & 31;
    int warp_m = wid >> 1;              // 0..1
    int warp_n = wid & 1;               // 0..1

    wmma::fragment<wmma::accumulator,16,16,8,float> acc[4][4];
    #pragma unroll
    for (int mt = 0; mt < 4; mt++)
        #pragma unroll
        for (int nt = 0; nt < 4; nt++)
            wmma::fill_fragment(acc[mt][nt], 0.0f);

    int lrow = tid >> 3;                // 0..15
    int lc4  = (tid & 7) * 4;

    {
        float* A = sh; float* B = sh + STAGE;
        #pragma unroll
        for (int u = 0; u < 8; u++) {
            int row = lrow + 16*u;
            cp16(&A[row*LDA + lc4], Ag + (size_t)row*DD + lc4);
            cp16(&B[row*LDA + lc4], Bg + (size_t)row*DD + lc4);
        }
        asm volatile("cp.async.commit_group;");
    }

    for (int kc = 0; kc < 8; kc++) {
        if (kc < 7) {
            float* A = sh + ((kc+1)&1)*2*STAGE;
            float* B = A + STAGE;
            int k0 = (kc+1)*32;
            #pragma unroll
            for (int u = 0; u < 8; u++) {
                int row = lrow + 16*u;
                cp16(&A[row*LDA + lc4], Ag + (size_t)row*DD + k0 + lc4);
                cp16(&B[row*LDA + lc4], Bg + (size_t)row*DD + k0 + lc4);
            }
            asm volatile("cp.async.commit_group;");
            asm volatile("cp.async.wait_group 1;");
        } else {
            asm volatile("cp.async.wait_group 0;");
        }
        __syncthreads();
        const float* A = sh + (kc&1)*2*STAGE;
        const float* B = A + STAGE;
        #pragma unroll
        for (int ks = 0; ks < 4; ks++) {
            wmma::fragment<wmma::matrix_a,16,16,8,wmma::precision::tf32,wmma::row_major> af[4];
            wmma::fragment<wmma::matrix_b,16,16,8,wmma::precision::tf32,wmma::col_major> bf[4];
            #pragma unroll
            for (int mt = 0; mt < 4; mt++)
                wmma::load_matrix_sync(af[mt], &A[(warp_m*64 + mt*16)*LDA + ks*8], LDA);
            #pragma unroll
            for (int nt = 0; nt < 4; nt++)
                wmma::load_matrix_sync(bf[nt], &B[(warp_n*64 + nt*16)*LDA + ks*8], LDA);
            #pragma unroll
            for (int mt = 0; mt < 4; mt++)
                #pragma unroll
                for (int nt = 0; nt < 4; nt++)
                    wmma::mma_sync(acc[mt][nt], af[mt], bf[nt], acc[mt][nt]);
        }
        __syncthreads();
    }

    if (hingeblk) {
        // hinge epilogue: sum relu(0.1 - v) over fragments (deterministic order)
        float loc = 0.f;
        #pragma unroll
        for (int mt = 0; mt < 4; mt++)
            #pragma unroll
            for (int nt = 0; nt < 4; nt++)
                #pragma unroll
                for (int e = 0; e < acc[mt][nt].num_elements; e++)
                    loc += fmaxf(0.1f - acc[mt][nt].x[e], 0.0f);
        __shared__ float red[4];
        #pragma unroll
        for (int o = 16; o; o >>= 1) loc += __shfl_xor_sync(0xffffffffu, loc, o);
        if (lane == 0) red[wid] = loc;
        __syncthreads();
        if (tid == 0)
            d_hpart[b*9 + (blockIdx.y - 4)*3 + (blockIdx.x - 4)] =
                (red[0] + red[1]) + (red[2] + red[3]);
        return;
    }

    // sim epilogue: store acc to sh[128][LDE], thread-per-row exp + sums
    #pragma unroll
    for (int mt = 0; mt < 4; mt++)
        #pragma unroll
        for (int nt = 0; nt < 4; nt++)
            wmma::store_matrix_sync(&sh[(warp_m*64 + mt*16)*LDE + warp_n*64 + nt*16],
                                    acc[mt][nt], LDE, wmma::mem_row_major);
    __syncthreads();

    bool inblk = (m0 < NR) && (n0 < NR);
    int ig = m0 + tid;
    float rsum = 0.f;
    float* Srow = d_S + ((size_t)b*NR + ig)*NR + n0;
    #pragma unroll
    for (int q = 0; q < 32; q++) {
        float4 v4 = *(float4*)&sh[tid*LDE + q*4];
        v4.x = fexp2v(L2E10 * v4.x);
        v4.y = fexp2v(L2E10 * v4.y);
        v4.z = fexp2v(L2E10 * v4.z);
        v4.w = fexp2v(L2E10 * v4.w);
        rsum += (v4.x + v4.y) + (v4.z + v4.w);
        *(float4*)&sh[tid*LDE + q*4] = v4;
        if (inblk) *(float4*)(Srow + q*4) = v4;
    }
    d_srp[((size_t)b*7 + (n0 >> 7))*NT + ig] = rsum;
    __syncthreads();

    float cs = 0.f;
    #pragma unroll 8
    for (int r = 0; r < 128; r++) cs += sh[r*LDE + tid];
    d_scp[((size_t)b*7 + (m0 >> 7))*NT + n0 + tid] = cs;
}

// ---------------- 3) cost (with fused partial-sum reduction): C = 1 - s/(sc+sr-s) + C^T ----------------
__global__ void k_cost()
{
    int b  = blockIdx.z;
    int j0 = blockIdx.x * 32, i0 = blockIdx.y * 32;
    float* S  = d_S  + (size_t)b * NR * NR;
    float* CT = d_CT + (size_t)b * NR * NR;
    __shared__ float tile[32][33];
    __shared__ float srv[32];
    __shared__ float scv[32];
    int tx = threadIdx.x, ty = threadIdx.y;   // (32, 8)
    int tid = ty*32 + tx;

    if (tid < 64) {
        int which = tid >> 5;    // 0: col sums, 1: row sums
        int idx   = tid & 31;
        const float* P = which ? (d_srp + (size_t)b*7*NT + i0 + idx)
                               : (d_scp + (size_t)b*7*NT + j0 + idx);
        float s = 0.f;
        #pragma unroll
        for (int t = 0; t < 7; t++) s += P[(size_t)t*NT];
        (which ? srv : scv)[idx] = s;
    }
    __syncthreads();

    int j = j0 + tx;
    float sc_j = scv[tx];
    #pragma unroll
    for (int r = 0; r < 4; r++) {
        int i = i0 + ty + 8*r;
        float s   = S[(size_t)i * NR + j];
        float den = sc_j + srv[ty + 8*r] - s;
        float c   = fmaf(-s, frcp(den), 1.0f);
        S[(size_t)i * NR + j] = c;
        tile[ty + 8*r][tx] = c;
    }
    __syncthreads();
    #pragma unroll
    for (int r = 0; r < 4; r++) {
        int ii = j0 + ty + 8*r;
        int jj = i0 + tx;
        CT[(size_t)ii * NR + jj] = tile[tx][ty + 8*r];
    }
}

// ---------------- 4) softmin: warp per row, exp2-domain, 1024-block single wave ----------------
__global__ void __launch_bounds__(256) k_softmin_pair(
    const float* __restrict__ hf, const float* __restrict__ hg,
    const float* __restrict__ oldf, const float* __restrict__ oldg,
    float* __restrict__ outf, float* __restrict__ outg,
    float eps, float keps, int avg)
{
    int lane   = threadIdx.x & 31;
    int warp0  = blockIdx.x * 8 + (threadIdx.x >> 5);
    int stride = gridDim.x * 8;

    for (int gw = warp0; gw < 2*BB*NR; gw += stride) {
        int side = (gw >= BB*NR) ? 1 : 0;
        int row  = side ? gw - BB*NR : gw;
        int b    = row >> 9;
        const float* Crow = (side ? d_CT : d_S) + (size_t)row * NR;
        const float* hv   = side ? hg : hf;
        const float* oldv = side ? oldg : oldf;
        float*       ov   = side ? outg : outf;
        const float* hb   = hv ? hv + (b << 9) : nullptr;

        float a[16];
        #pragma unroll
        for (int q = 0; q < 4; q++) {
            int j = q*128 + lane*4;
            float4 c4 = *(const float4*)(Crow + j);
            if (hb) {
                float4 h4 = *(const float4*)(hb + j);
                a[q*4+0] = (h4.x - c4.x) * keps;
                a[q*4+1] = (h4.y - c4.y) * keps;
                a[q*4+2] = (h4.z - c4.z) * keps;
                a[q*4+3] = (h4.w - c4.w) * keps;
            } else {
                a[q*4+0] = -c4.x * keps;
                a[q*4+1] = -c4.y * keps;
                a[q*4+2] = -c4.z * keps;
                a[q*4+3] = -c4.w * keps;
            }
        }
        float m = a[0];
        #pragma unroll
        for (int u = 1; u < 16; u++) m = fmaxf(m, a[u]);
        #pragma unroll
        for (int o = 16; o; o >>= 1) m = fmaxf(m, __shfl_xor_sync(0xffffffffu, m, o));

        float s0 = 0.f, s1 = 0.f;
        #pragma unroll
        for (int u = 0; u < 8; u++) {
            float sc0, sc1;
            float p0 = fexp2s(a[2*u]   - m, sc0);
            float p1 = fexp2s(a[2*u+1] - m, sc1);
            s0 = fmaf(p0, sc0, s0);
            s1 = fmaf(p1, sc1, s1);
        }
        float s = s0 + s1;
        #pragma unroll
        for (int o = 16; o; o >>= 1) s += __shfl_xor_sync(0xffffffffu, s, o);
        if (lane == 0) {
            float val = -eps * (fmaf(m, 0.69314718055994531f, logf(s)));
            if (avg) val = 0.5f * (oldv[row] + val);
            ov[row] = val;
        }
    }
}

// ---------------- 5) deterministic final reduction ----------------
__global__ void k_finalize(float* __restrict__ out)
{
    int t = threadIdx.x;
    double acc = 0.0;
    for (int idx = t; idx < BB*NR; idx += 256)
        acc += (double)d_du2[idx] + (double)d_du3[idx];
    double h = 0.0;
    for (int idx = t; idx < 144; idx += 256) h += (double)d_hpart[idx];
    __shared__ double sa[256];
    __shared__ double sb[256];
    sa[t] = acc; sb[t] = h;
    __syncthreads();
    for (int o = 128; o; o >>= 1) {
        if (t < o) { sa[t] += sa[t + o]; sb[t] += sb[t + o]; }
        __syncthreads();
    }
    if (t == 0) {
        out[0] = (float)sb[0];
        out[1] = (float)(sa[0] / (double)BB);
    }
}

// ---------------- host ----------------
extern "C" void kernel_launch(void* const* d_in, const int* in_sizes, int n_in,
                              void* d_out, int out_size)
{
    const float* x1 = (const float*)d_in[0];
    const float* x2 = (const float*)d_in[1];
    const float* x3 = (const float*)d_in[2];
    const float* x4 = (const float*)d_in[3];
    float* out = (float*)d_out;

    cudaFuncSetAttribute(k_simgemm, cudaFuncAttributeMaxDynamicSharedMemorySize, SIM_SMEM);

    float *p0, *p1, *p2, *p3;
    cudaGetSymbolAddress((void**)&p0, d_du0);
    cudaGetSymbolAddress((void**)&p1, d_du1);
    cudaGetSymbolAddress((void**)&p2, d_du2);
    cudaGetSymbolAddress((void**)&p3, d_du3);

    k_normalize<<<2*BB*NT/8, 256>>>(x1, x2, x3, x4);
    k_simgemm<<<dim3(7, 7, BB), 128, SIM_SMEM>>>();
    k_cost<<<dim3(NR/32, NR/32, BB), dim3(32, 8)>>>();

    const float EPS[8] = {9.0f, 9.0f, 2.25f, 0.5625f, 0.140625f,
                          0.03515625f, 0.0087890625f, 0.0025f};
    const float L2E = 1.4426950408889634f;

    // 1024 blocks: 8192 warps, exactly 2 rows per warp, one fully-resident wave
    k_softmin_pair<<<1024, 256>>>(nullptr, nullptr, nullptr, nullptr,
                                  p0, p1, 9.0f, L2E/9.0f, 0);

    float *fc = p0, *gc = p1, *fa = p2, *ga = p3;
    for (int k = 0; k < 8; k++) {
        float e = EPS[k];
        k_softmin_pair<<<1024, 256>>>(gc, fc, fc, gc, fa, ga, e, L2E/e, 1);
        float* tf = fc; fc = fa; fa = tf;
        float* tg = gc; gc = ga; ga = tg;
    }
    k_softmin_pair<<<1024, 256>>>(gc, fc, nullptr, nullptr, p2, p3,
                                  0.0025f, L2E/0.0025f, 0);

    k_finalize<<<1, 256>>>(out);
}

// round 15
// speedup vs baseline: 1.3125x; 1.0288x over previous
#include <cuda_runtime.h>
#include <cuda_fp16.h>
#include <cstdint>
#include <mma.h>
#include <math.h>

using namespace nvcuda;

#define BB 16      // batch
#define NR 512     // real points
#define NP 384     // padding points
#define NT 896     // total points per side
#define DD 256     // feature dim

// ---------------- scratch ----------------
__device__ float  d_f1n[BB*NT*DD];      // normalized f1 (tf32-rounded)
__device__ float  d_f2n[BB*NT*DD];      // normalized f2 (tf32-rounded)
__device__ float  d_x3r[BB*NP*DD];      // tf32-rounded raw x3
__device__ float  d_x4r[BB*NP*DD];      // tf32-rounded raw x4
__device__ float  d_S  [BB*NR*NR];      // S (fp32, from simgemm)
__device__ __half d_Ch [BB*NR*NR];      // C  in fp16
__device__ __half d_CTh[BB*NR*NR];      // C^T in fp16
__device__ float  d_srp[BB*7*NT];
__device__ float  d_scp[BB*7*NT];
__device__ float  d_du0[BB*NR];
__device__ float  d_du1[BB*NR];
__device__ float  d_du2[BB*NR];
__device__ float  d_du3[BB*NR];
__device__ float  d_hpart[144];

// ---------------- FMA-only helpers ----------------
// 2^y, clamped below at -125.  Degree-6 poly in r = y - round(y).
__device__ __forceinline__ float fexp2s(float y, float& scale) {
    y = fmaxf(y, -125.0f);
    float Y = y + 12582912.0f;           // round-to-nearest-int magic
    int   n = __float_as_int(Y);
    float fi = Y - 12582912.0f;
    float r = y - fi;                    // r in [-0.5, 0.5]
    float p =           1.5403530e-4f;   // (ln2)^6/720
    p = fmaf(p, r, 1.3333558e-3f);
    p = fmaf(p, r, 9.6181291e-3f);
    p = fmaf(p, r, 5.5504109e-2f);
    p = fmaf(p, r, 2.4022651e-1f);
    p = fmaf(p, r, 6.9314718e-1f);
    p = fmaf(p, r, 1.0f);
    scale = __int_as_float((unsigned)((n - 0x4B400000 + 127) << 23));
    return p;
}

__device__ __forceinline__ float fexp2v(float y) {
    float s;
    float p = fexp2s(y, s);
    return p * s;
}

__device__ __forceinline__ float frcp(float x) {
    float r = __int_as_float(0x7EF311C3 - __float_as_int(x));
    r = r * fmaf(-x, r, 2.0f);
    r = r * fmaf(-x, r, 2.0f);
    r = r * fmaf(-x, r, 2.0f);
    return r;
}

__device__ __forceinline__ void cp16(void* s, const void* g) {
    unsigned int sa = (unsigned int)__cvta_generic_to_shared(s);
    asm volatile("cp.async.cg.shared.global [%0], [%1], 16;" :: "r"(sa), "l"(g));
}

__device__ __forceinline__ float4 tf32x4(float4 v) {
    v.x = wmma::__float_to_tf32(v.x);
    v.y = wmma::__float_to_tf32(v.y);
    v.z = wmma::__float_to_tf32(v.z);
    v.w = wmma::__float_to_tf32(v.w);
    return v;
}

// ---------------- 1) normalize + tf32-round; also emit rounded raw x3/x4 ----------------
__global__ void __launch_bounds__(256) k_normalize(
    const float* __restrict__ x1, const float* __restrict__ x2,
    const float* __restrict__ x3, const float* __restrict__ x4)
{
    int gw   = blockIdx.x * 8 + (threadIdx.x >> 5);
    int lane = threadIdx.x & 31;
    int which = (gw >= BB*NT) ? 1 : 0;
    int r     = which ? gw - BB*NT : gw;
    int b = r / NT, i = r % NT;
    const float* src;
    float* rawdst = nullptr;
    if (i < NR) {
        src = (which ? x2 : x1) + ((size_t)(b*NR + i)) * DD;
    } else {
        size_t off = ((size_t)(b*NP + (i - NR))) * DD;
        src = (which ? x4 : x3) + off;
        rawdst = (which ? d_x4r : d_x3r) + off;
    }
    float* dst = (which ? d_f2n : d_f1n) + (size_t)r * DD;

    float4 v0 = *(const float4*)(src + lane*4);
    float4 v1 = *(const float4*)(src + 128 + lane*4);
    if (rawdst) {
        *(float4*)(rawdst + lane*4)       = tf32x4(v0);
        *(float4*)(rawdst + 128 + lane*4) = tf32x4(v1);
    }
    float sq = v0.x*v0.x + v0.y*v0.y + v0.z*v0.z + v0.w*v0.w
             + v1.x*v1.x + v1.y*v1.y + v1.z*v1.z + v1.w*v1.w;
    #pragma unroll
    for (int o = 16; o; o >>= 1) sq += __shfl_xor_sync(0xffffffffu, sq, o);
    float rn = 1.0f / fmaxf(sqrtf(sq), 1e-12f);
    v0.x *= rn; v0.y *= rn; v0.z *= rn; v0.w *= rn;
    v1.x *= rn; v1.y *= rn; v1.z *= rn; v1.w *= rn;
    *(float4*)(dst + lane*4)       = tf32x4(v0);
    *(float4*)(dst + 128 + lane*4) = tf32x4(v1);
}

// ---------------- 2) pipelined tf32 GEMM, 4 warps x (64x64 tiles) ----------------
#define LDA 36                // ≡4 mod 32 -> conflict-free fragment loads
#define LDE 132
#define STAGE (128*LDA)       // 4608 floats
#define SIM_SMEM (4*STAGE*4)  // 73728 bytes (>= 128*LDE*4 = 67584 for epilogue)
#define L2E10 14.4269504088896340736f   // 10 * log2(e)

__global__ void __launch_bounds__(128) k_simgemm()
{
    extern __shared__ float sh[];

    int b  = blockIdx.z;
    int m0 = blockIdx.y * 128, n0 = blockIdx.x * 128;
    if (m0 >= NR && n0 >= NR) return;   // padding x padding feeds nothing

    const float* Ag = d_f1n + (size_t)b * NT * DD + (size_t)m0 * DD;
    const float* Bg = d_f2n + (size_t)b * NT * DD + (size_t)n0 * DD;

    int tid = threadIdx.x;              // 128 threads, 4 warps
    int wid = tid >> 5;
    int warp_m = wid >> 1;              // 0..1
    int warp_n = wid & 1;               // 0..1

    wmma::fragment<wmma::accumulator,16,16,8,float> acc[4][4];
    #pragma unroll
    for (int mt = 0; mt < 4; mt++)
        #pragma unroll
        for (int nt = 0; nt < 4; nt++)
            wmma::fill_fragment(acc[mt][nt], 0.0f);

    int lrow = tid >> 3;                // 0..15
    int lc4  = (tid & 7) * 4;

    {
        float* A = sh; float* B = sh + STAGE;
        #pragma unroll
        for (int u = 0; u < 8; u++) {
            int row = lrow + 16*u;
            cp16(&A[row*LDA + lc4], Ag + (size_t)row*DD + lc4);
            cp16(&B[row*LDA + lc4], Bg + (size_t)row*DD + lc4);
        }
        asm volatile("cp.async.commit_group;");
    }

    for (int kc = 0; kc < 8; kc++) {
        if (kc < 7) {
            float* A = sh + ((kc+1)&1)*2*STAGE;
            float* B = A + STAGE;
            int k0 = (kc+1)*32;
            #pragma unroll
            for (int u = 0; u < 8; u++) {
                int row = lrow + 16*u;
                cp16(&A[row*LDA + lc4], Ag + (size_t)row*DD + k0 + lc4);
                cp16(&B[row*LDA + lc4], Bg + (size_t)row*DD + k0 + lc4);
            }
            asm volatile("cp.async.commit_group;");
            asm volatile("cp.async.wait_group 1;");
        } else {
            asm volatile("cp.async.wait_group 0;");
        }
        __syncthreads();
        const float* A = sh + (kc&1)*2*STAGE;
        const float* B = A + STAGE;
        #pragma unroll
        for (int ks = 0; ks < 4; ks++) {
            wmma::fragment<wmma::matrix_a,16,16,8,wmma::precision::tf32,wmma::row_major> af[4];
            wmma::fragment<wmma::matrix_b,16,16,8,wmma::precision::tf32,wmma::col_major> bf[4];
            #pragma unroll
            for (int mt = 0; mt < 4; mt++)
                wmma::load_matrix_sync(af[mt], &A[(warp_m*64 + mt*16)*LDA + ks*8], LDA);
            #pragma unroll
            for (int nt = 0; nt < 4; nt++)
                wmma::load_matrix_sync(bf[nt], &B[(warp_n*64 + nt*16)*LDA + ks*8], LDA);
            #pragma unroll
            for (int mt = 0; mt < 4; mt++)
                #pragma unroll
                for (int nt = 0; nt < 4; nt++)
                    wmma::mma_sync(acc[mt][nt], af[mt], bf[nt], acc[mt][nt]);
        }
        __syncthreads();
    }

    // epilogue: store acc to sh[128][LDE], thread-per-row exp + sums
    #pragma unroll
    for (int mt = 0; mt < 4; mt++)
        #pragma unroll
        for (int nt = 0; nt < 4; nt++)
            wmma::store_matrix_sync(&sh[(warp_m*64 + mt*16)*LDE + warp_n*64 + nt*16],
                                    acc[mt][nt], LDE, wmma::mem_row_major);
    __syncthreads();

    bool inblk = (m0 < NR) && (n0 < NR);
    int ig = m0 + tid;
    float rsum = 0.f;
    float* Srow = d_S + ((size_t)b*NR + ig)*NR + n0;
    #pragma unroll
    for (int q = 0; q < 32; q++) {
        float4 v4 = *(float4*)&sh[tid*LDE + q*4];
        v4.x = fexp2v(L2E10 * v4.x);
        v4.y = fexp2v(L2E10 * v4.y);
        v4.z = fexp2v(L2E10 * v4.z);
        v4.w = fexp2v(L2E10 * v4.w);
        rsum += (v4.x + v4.y) + (v4.z + v4.w);
        *(float4*)&sh[tid*LDE + q*4] = v4;
        if (inblk) *(float4*)(Srow + q*4) = v4;
    }
    d_srp[((size_t)b*7 + (n0 >> 7))*NT + ig] = rsum;
    __syncthreads();

    float cs = 0.f;
    #pragma unroll 8
    for (int r = 0; r < 128; r++) cs += sh[r*LDE + tid];
    d_scp[((size_t)b*7 + (m0 >> 7))*NT + n0 + tid] = cs;
}

// ---------------- 3) cost (fused partial-sum reduce): C = 1 - s/(sc+sr-s), fp16 C + C^T ----------------
__global__ void k_cost()
{
    int b  = blockIdx.z;
    int j0 = blockIdx.x * 32, i0 = blockIdx.y * 32;
    const float* S = d_S + (size_t)b * NR * NR;
    __half* Ch  = d_Ch  + (size_t)b * NR * NR;
    __half* CTh = d_CTh + (size_t)b * NR * NR;
    __shared__ float tile[32][33];
    __shared__ float srv[32];
    __shared__ float scv[32];
    int tx = threadIdx.x, ty = threadIdx.y;   // (32, 8)
    int tid = ty*32 + tx;

    if (tid < 64) {
        int which = tid >> 5;    // 0: col sums, 1: row sums
        int idx   = tid & 31;
        const float* P = which ? (d_srp + (size_t)b*7*NT + i0 + idx)
                               : (d_scp + (size_t)b*7*NT + j0 + idx);
        float s = 0.f;
        #pragma unroll
        for (int t = 0; t < 7; t++) s += P[(size_t)t*NT];
        (which ? srv : scv)[idx] = s;
    }
    __syncthreads();

    int j = j0 + tx;
    float sc_j = scv[tx];
    #pragma unroll
    for (int r = 0; r < 4; r++) {
        int i = i0 + ty + 8*r;
        float s   = S[(size_t)i * NR + j];
        float den = sc_j + srv[ty + 8*r] - s;
        float c   = fmaf(-s, frcp(den), 1.0f);
        Ch[(size_t)i * NR + j] = __float2half_rn(c);
        tile[ty + 8*r][tx] = c;
    }
    __syncthreads();
    #pragma unroll
    for (int r = 0; r < 4; r++) {
        int ii = j0 + ty + 8*r;
        int jj = i0 + tx;
        CTh[(size_t)ii * NR + jj] = __float2half_rn(tile[tx][ty + 8*r]);
    }
}

// ---------------- 4) softmin: warp per row, fp16 C rows, exp2-domain ----------------
__global__ void __launch_bounds__(256) k_softmin_pair(
    const float* __restrict__ hf, const float* __restrict__ hg,
    const float* __restrict__ oldf, const float* __restrict__ oldg,
    float* __restrict__ outf, float* __restrict__ outg,
    float eps, float keps, int avg)
{
    int lane   = threadIdx.x & 31;
    int warp0  = blockIdx.x * 8 + (threadIdx.x >> 5);
    int stride = gridDim.x * 8;

    for (int gw = warp0; gw < 2*BB*NR; gw += stride) {
        int side = (gw >= BB*NR) ? 1 : 0;
        int row  = side ? gw - BB*NR : gw;
        int b    = row >> 9;
        const __half* Crow = (side ? d_CTh : d_Ch) + (size_t)row * NR;
        const float* hv   = side ? hg : hf;
        const float* oldv = side ? oldg : oldf;
        float*       ov   = side ? outg : outf;
        const float* hb   = hv ? hv + (b << 9) : nullptr;

        float a[16];
        #pragma unroll
        for (int q = 0; q < 4; q++) {
            int j = q*128 + lane*4;
            uint2 cc = *(const uint2*)(Crow + j);
            float2 c01 = __half22float2(*reinterpret_cast<__half2*>(&cc.x));
            float2 c23 = __half22float2(*reinterpret_cast<__half2*>(&cc.y));
            if (hb) {
                float4 h4 = *(const float4*)(hb + j);
                a[q*4+0] = (h4.x - c01.x) * keps;
                a[q*4+1] = (h4.y - c01.y) * keps;
                a[q*4+2] = (h4.z - c23.x) * keps;
                a[q*4+3] = (h4.w - c23.y) * keps;
            } else {
                a[q*4+0] = -c01.x * keps;
                a[q*4+1] = -c01.y * keps;
                a[q*4+2] = -c23.x * keps;
                a[q*4+3] = -c23.y * keps;
            }
        }
        float m = a[0];
        #pragma unroll
        for (int u = 1; u < 16; u++) m = fmaxf(m, a[u]);
        #pragma unroll
        for (int o = 16; o; o >>= 1) m = fmaxf(m, __shfl_xor_sync(0xffffffffu, m, o));

        float s0 = 0.f, s1 = 0.f;
        #pragma unroll
        for (int u = 0; u < 8; u++) {
            float sc0, sc1;
            float p0 = fexp2s(a[2*u]   - m, sc0);
            float p1 = fexp2s(a[2*u+1] - m, sc1);
            s0 = fmaf(p0, sc0, s0);
            s1 = fmaf(p1, sc1, s1);
        }
        float s = s0 + s1;
        #pragma unroll
        for (int o = 16; o; o >>= 1) s += __shfl_xor_sync(0xffffffffu, s, o);
        if (lane == 0) {
            float val = -eps * (fmaf(m, 0.69314718055994531f, logf(s)));
            if (avg) val = 0.5f * (oldv[row] + val);
            ov[row] = val;
        }
    }
}

// ---------------- 5) hinge GEMM (pipelined tf32, pre-rounded inputs) ----------------
__global__ void __launch_bounds__(256) k_hinge()
{
    extern __shared__ float sh[];
    int b  = blockIdx.z;
    int m0 = blockIdx.y * 128, n0 = blockIdx.x * 128;
    const float* Ag = d_x3r + (size_t)b * NP * DD + (size_t)m0 * DD;
    const float* Bg = d_x4r + (size_t)b * NP * DD + (size_t)n0 * DD;

    int tid = threadIdx.x;
    int wid = tid >> 5;
    int warp_m = wid >> 2;
    int warp_n = wid & 3;

    wmma::fragment<wmma::accumulator,16,16,8,float> acc[4][2];
    #pragma unroll
    for (int mt = 0; mt < 4; mt++)
        #pragma unroll
        for (int nt = 0; nt < 2; nt++)
            wmma::fill_fragment(acc[mt][nt], 0.0f);

    int lrow = tid >> 3;
    int lc4  = (tid & 7) * 4;

    {
        float* A = sh; float* B = sh + STAGE;
        #pragma unroll
        for (int u = 0; u < 4; u++) {
            int row = lrow + 32*u;
            cp16(&A[row*LDA + lc4], Ag + (size_t)row*DD + lc4);
            cp16(&B[row*LDA + lc4], Bg + (size_t)row*DD + lc4);
        }
        asm volatile("cp.async.commit_group;");
    }

    for (int kc = 0; kc < 8; kc++) {
        if (kc < 7) {
            float* A = sh + ((kc+1)&1)*2*STAGE;
            float* B = A + STAGE;
            int k0 = (kc+1)*32;
            #pragma unroll
            for (int u = 0; u < 4; u++) {
                int row = lrow + 32*u;
                cp16(&A[row*LDA + lc4], Ag + (size_t)row*DD + k0 + lc4);
                cp16(&B[row*LDA + lc4], Bg + (size_t)row*DD + k0 + lc4);
            }
            asm volatile("cp.async.commit_group;");
            asm volatile("cp.async.wait_group 1;");
        } else {
            asm volatile("cp.async.wait_group 0;");
        }
        __syncthreads();
        const float* A = sh + (kc&1)*2*STAGE;
        const float* B = A + STAGE;
        #pragma unroll
        for (int ks = 0; ks < 4; ks++) {
            wmma::fragment<wmma::matrix_b,16,16,8,wmma::precision::tf32,wmma::col_major> bf[2];
            #pragma unroll
            for (int nt = 0; nt < 2; nt++)
                wmma::load_matrix_sync(bf[nt], &B[(warp_n*32 + nt*16)*LDA + ks*8], LDA);
            #pragma unroll
            for (int mt = 0; mt < 4; mt++) {
                wmma::fragment<wmma::matrix_a,16,16,8,wmma::precision::tf32,wmma::row_major> af;
                wmma::load_matrix_sync(af, &A[(warp_m*64 + mt*16)*LDA + ks*8], LDA);
                #pragma unroll
                for (int nt = 0; nt < 2; nt++)
                    wmma::mma_sync(acc[mt][nt], af, bf[nt], acc[mt][nt]);
            }
        }
        __syncthreads();
    }

    float loc = 0.f;
    #pragma unroll
    for (int mt = 0; mt < 4; mt++)
        #pragma unroll
        for (int nt = 0; nt < 2; nt++)
            #pragma unroll
            for (int e = 0; e < acc[mt][nt].num_elements; e++)
                loc += fmaxf(0.1f - acc[mt][nt].x[e], 0.0f);

    __shared__ float red[8];
    #pragma unroll
    for (int o = 16; o; o >>= 1) loc += __shfl_xor_sync(0xffffffffu, loc, o);
    if ((tid & 31) == 0) red[tid >> 5] = loc;
    __syncthreads();
    if (tid == 0) {
        float tot = 0.f;
        #pragma unroll
        for (int w = 0; w < 8; w++) tot += red[w];
        d_hpart[blockIdx.z * 9 + blockIdx.y * 3 + blockIdx.x] = tot;
    }
}

// ---------------- 6) deterministic final reduction ----------------
__global__ void k_finalize(float* __restrict__ out)
{
    int t = threadIdx.x;
    double acc = 0.0;
    for (int idx = t; idx < BB*NR; idx += 256)
        acc += (double)d_du2[idx] + (double)d_du3[idx];
    double h = 0.0;
    for (int idx = t; idx < 144; idx += 256) h += (double)d_hpart[idx];
    __shared__ double sa[256];
    __shared__ double sb[256];
    sa[t] = acc; sb[t] = h;
    __syncthreads();
    for (int o = 128; o; o >>= 1) {
        if (t < o) { sa[t] += sa[t + o]; sb[t] += sb[t + o]; }
        __syncthreads();
    }
    if (t == 0) {
        out[0] = (float)sb[0];
        out[1] = (float)(sa[0] / (double)BB);
    }
}

// ---------------- host ----------------
extern "C" void kernel_launch(void* const* d_in, const int* in_sizes, int n_in,
                              void* d_out, int out_size)
{
    const float* x1 = (const float*)d_in[0];
    const float* x2 = (const float*)d_in[1];
    const float* x3 = (const float*)d_in[2];
    const float* x4 = (const float*)d_in[3];
    float* out = (float*)d_out;

    cudaFuncSetAttribute(k_simgemm, cudaFuncAttributeMaxDynamicSharedMemorySize, SIM_SMEM);
    cudaFuncSetAttribute(k_hinge,   cudaFuncAttributeMaxDynamicSharedMemorySize, SIM_SMEM);

    float *p0, *p1, *p2, *p3;
    cudaGetSymbolAddress((void**)&p0, d_du0);
    cudaGetSymbolAddress((void**)&p1, d_du1);
    cudaGetSymbolAddress((void**)&p2, d_du2);
    cudaGetSymbolAddress((void**)&p3, d_du3);

    k_normalize<<<2*BB*NT/8, 256>>>(x1, x2, x3, x4);
    k_simgemm<<<dim3(7, 7, BB), 128, SIM_SMEM>>>();
    k_cost<<<dim3(NR/32, NR/32, BB), dim3(32, 8)>>>();
    k_hinge<<<dim3(3, 3, BB), 256, SIM_SMEM>>>();

    const float EPS[8] = {9.0f, 9.0f, 2.25f, 0.5625f, 0.140625f,
                          0.03515625f, 0.0087890625f, 0.0025f};
    const float L2E = 1.4426950408889634f;

    // 1024 blocks: 8192 warps, exactly 2 rows per warp, one fully-resident wave
    k_softmin_pair<<<1024, 256>>>(nullptr, nullptr, nullptr, nullptr,
                                  p0, p1, 9.0f, L2E/9.0f, 0);

    float *fc = p0, *gc = p1, *fa = p2, *ga = p3;
    for (int k = 0; k < 8; k++) {
        float e = EPS[k];
        k_softmin_pair<<<1024, 256>>>(gc, fc, fc, gc, fa, ga, e, L2E/e, 1);
        float* tf = fc; fc = fa; fa = tf;
        float* tg = gc; gc = ga; ga = tg;
    }
    k_softmin_pair<<<1024, 256>>>(gc, fc, nullptr, nullptr, p2, p3,
                                  0.0025f, L2E/0.0025f, 0);

    k_finalize<<<1, 256>>>(out);
}

// round 16
// speedup vs baseline: 1.3188x; 1.0048x over previous
#include <cuda_runtime.h>
#include <cuda_fp16.h>
#include <cstdint>
#include <mma.h>
#include <math.h>

using namespace nvcuda;

#define BB 16      // batch
#define NR 512     // real points
#define NP 384     // padding points
#define NT 896     // total points per side
#define DD 256     // feature dim

// ---------------- scratch ----------------
__device__ float  d_f1n[BB*NT*DD];      // normalized f1 (tf32-rounded)
__device__ float  d_f2n[BB*NT*DD];      // normalized f2 (tf32-rounded)
__device__ float  d_x3r[BB*NP*DD];      // tf32-rounded raw x3
__device__ float  d_x4r[BB*NP*DD];      // tf32-rounded raw x4
__device__ __half d_Sh [BB*NR*NR];      // S in fp16 (from simgemm)
__device__ __half d_Ch [BB*NR*NR];      // C  in fp16
__device__ __half d_CTh[BB*NR*NR];      // C^T in fp16
__device__ float  d_srp[BB*7*NT];
__device__ float  d_scp[BB*7*NT];
__device__ float  d_du0[BB*NR];
__device__ float  d_du1[BB*NR];
__device__ float  d_du2[BB*NR];
__device__ float  d_du3[BB*NR];
__device__ float  d_hpart[576];

// ---------------- FMA-only helpers ----------------
// 2^y, clamped below at -125.  Degree-4 poly in r = y - round(y)  (max rel err ~6e-5).
__device__ __forceinline__ float fexp2s(float y, float& scale) {
    y = fmaxf(y, -125.0f);
    float Y = y + 12582912.0f;           // round-to-nearest-int magic
    int   n = __float_as_int(Y);
    float fi = Y - 12582912.0f;
    float r = y - fi;                    // r in [-0.5, 0.5]
    float p =           9.6181291e-3f;   // (ln2)^4/24
    p = fmaf(p, r, 5.5504109e-2f);
    p = fmaf(p, r, 2.4022651e-1f);
    p = fmaf(p, r, 6.9314718e-1f);
    p = fmaf(p, r, 1.0f);
    scale = __int_as_float((unsigned)((n - 0x4B400000 + 127) << 23));
    return p;
}

__device__ __forceinline__ float fexp2v(float y) {
    float s;
    float p = fexp2s(y, s);
    return p * s;
}

__device__ __forceinline__ float frcp(float x) {
    float r = __int_as_float(0x7EF311C3 - __float_as_int(x));
    r = r * fmaf(-x, r, 2.0f);
    r = r * fmaf(-x, r, 2.0f);
    r = r * fmaf(-x, r, 2.0f);
    return r;
}

__device__ __forceinline__ void cp16(void* s, const void* g) {
    unsigned int sa = (unsigned int)__cvta_generic_to_shared(s);
    asm volatile("cp.async.cg.shared.global [%0], [%1], 16;" :: "r"(sa), "l"(g));
}

__device__ __forceinline__ float4 tf32x4(float4 v) {
    v.x = wmma::__float_to_tf32(v.x);
    v.y = wmma::__float_to_tf32(v.y);
    v.z = wmma::__float_to_tf32(v.z);
    v.w = wmma::__float_to_tf32(v.w);
    return v;
}

// ---------------- 1) normalize + tf32-round; also emit rounded raw x3/x4 ----------------
__global__ void __launch_bounds__(256) k_normalize(
    const float* __restrict__ x1, const float* __restrict__ x2,
    const float* __restrict__ x3, const float* __restrict__ x4)
{
    int gw   = blockIdx.x * 8 + (threadIdx.x >> 5);
    int lane = threadIdx.x & 31;
    int which = (gw >= BB*NT) ? 1 : 0;
    int r     = which ? gw - BB*NT : gw;
    int b = r / NT, i = r % NT;
    const float* src;
    float* rawdst = nullptr;
    if (i < NR) {
        src = (which ? x2 : x1) + ((size_t)(b*NR + i)) * DD;
    } else {
        size_t off = ((size_t)(b*NP + (i - NR))) * DD;
        src = (which ? x4 : x3) + off;
        rawdst = (which ? d_x4r : d_x3r) + off;
    }
    float* dst = (which ? d_f2n : d_f1n) + (size_t)r * DD;

    float4 v0 = *(const float4*)(src + lane*4);
    float4 v1 = *(const float4*)(src + 128 + lane*4);
    if (rawdst) {
        *(float4*)(rawdst + lane*4)       = tf32x4(v0);
        *(float4*)(rawdst + 128 + lane*4) = tf32x4(v1);
    }
    float sq = v0.x*v0.x + v0.y*v0.y + v0.z*v0.z + v0.w*v0.w
             + v1.x*v1.x + v1.y*v1.y + v1.z*v1.z + v1.w*v1.w;
    #pragma unroll
    for (int o = 16; o; o >>= 1) sq += __shfl_xor_sync(0xffffffffu, sq, o);
    float rn = 1.0f / fmaxf(sqrtf(sq), 1e-12f);
    v0.x *= rn; v0.y *= rn; v0.z *= rn; v0.w *= rn;
    v1.x *= rn; v1.y *= rn; v1.z *= rn; v1.w *= rn;
    *(float4*)(dst + lane*4)       = tf32x4(v0);
    *(float4*)(dst + 128 + lane*4) = tf32x4(v1);
}

// ---------------- 2) pipelined tf32 GEMM, 4 warps x (64x64 tiles), fp16 S out ----------------
#define LDA 36                // ≡4 mod 32 -> conflict-free fragment loads
#define LDE 132
#define STAGE (128*LDA)       // 4608 floats
#define SIM_SMEM (4*STAGE*4)  // 73728 bytes (>= 128*LDE*4 = 67584 for epilogue)
#define L2E10 14.4269504088896340736f   // 10 * log2(e)

__global__ void __launch_bounds__(128) k_simgemm()
{
    extern __shared__ float sh[];

    int b  = blockIdx.z;
    int m0 = blockIdx.y * 128, n0 = blockIdx.x * 128;
    if (m0 >= NR && n0 >= NR) return;   // padding x padding feeds nothing

    const float* Ag = d_f1n + (size_t)b * NT * DD + (size_t)m0 * DD;
    const float* Bg = d_f2n + (size_t)b * NT * DD + (size_t)n0 * DD;

    int tid = threadIdx.x;              // 128 threads, 4 warps
    int wid = tid >> 5;
    int warp_m = wid >> 1;              // 0..1
    int warp_n = wid & 1;               // 0..1

    wmma::fragment<wmma::accumulator,16,16,8,float> acc[4][4];
    #pragma unroll
    for (int mt = 0; mt < 4; mt++)
        #pragma unroll
        for (int nt = 0; nt < 4; nt++)
            wmma::fill_fragment(acc[mt][nt], 0.0f);

    int lrow = tid >> 3;                // 0..15
    int lc4  = (tid & 7) * 4;

    {
        float* A = sh; float* B = sh + STAGE;
        #pragma unroll
        for (int u = 0; u < 8; u++) {
            int row = lrow + 16*u;
            cp16(&A[row*LDA + lc4], Ag + (size_t)row*DD + lc4);
            cp16(&B[row*LDA + lc4], Bg + (size_t)row*DD + lc4);
        }
        asm volatile("cp.async.commit_group;");
    }

    for (int kc = 0; kc < 8; kc++) {
        if (kc < 7) {
            float* A = sh + ((kc+1)&1)*2*STAGE;
            float* B = A + STAGE;
            int k0 = (kc+1)*32;
            #pragma unroll
            for (int u = 0; u < 8; u++) {
                int row = lrow + 16*u;
                cp16(&A[row*LDA + lc4], Ag + (size_t)row*DD + k0 + lc4);
                cp16(&B[row*LDA + lc4], Bg + (size_t)row*DD + k0 + lc4);
            }
            asm volatile("cp.async.commit_group;");
            asm volatile("cp.async.wait_group 1;");
        } else {
            asm volatile("cp.async.wait_group 0;");
        }
        __syncthreads();
        const float* A = sh + (kc&1)*2*STAGE;
        const float* B = A + STAGE;
        #pragma unroll
        for (int ks = 0; ks < 4; ks++) {
            wmma::fragment<wmma::matrix_a,16,16,8,wmma::precision::tf32,wmma::row_major> af[4];
            wmma::fragment<wmma::matrix_b,16,16,8,wmma::precision::tf32,wmma::col_major> bf[4];
            #pragma unroll
            for (int mt = 0; mt < 4; mt++)
                wmma::load_matrix_sync(af[mt], &A[(warp_m*64 + mt*16)*LDA + ks*8], LDA);
            #pragma unroll
            for (int nt = 0; nt < 4; nt++)
                wmma::load_matrix_sync(bf[nt], &B[(warp_n*64 + nt*16)*LDA + ks*8], LDA);
            #pragma unroll
            for (int mt = 0; mt < 4; mt++)
                #pragma unroll
                for (int nt = 0; nt < 4; nt++)
                    wmma::mma_sync(acc[mt][nt], af[mt], bf[nt], acc[mt][nt]);
        }
        __syncthreads();
    }

    // epilogue: store acc to sh[128][LDE], thread-per-row exp + sums, fp16 store
    #pragma unroll
    for (int mt = 0; mt < 4; mt++)
        #pragma unroll
        for (int nt = 0; nt < 4; nt++)
            wmma::store_matrix_sync(&sh[(warp_m*64 + mt*16)*LDE + warp_n*64 + nt*16],
                                    acc[mt][nt], LDE, wmma::mem_row_major);
    __syncthreads();

    bool inblk = (m0 < NR) && (n0 < NR);
    int ig = m0 + tid;
    float rsum = 0.f;
    __half* Srow = d_Sh + ((size_t)b*NR + ig)*NR + n0;
    #pragma unroll
    for (int q = 0; q < 32; q++) {
        float4 v4 = *(float4*)&sh[tid*LDE + q*4];
        v4.x = fexp2v(L2E10 * v4.x);
        v4.y = fexp2v(L2E10 * v4.y);
        v4.z = fexp2v(L2E10 * v4.z);
        v4.w = fexp2v(L2E10 * v4.w);
        rsum += (v4.x + v4.y) + (v4.z + v4.w);
        *(float4*)&sh[tid*LDE + q*4] = v4;
        if (inblk) {
            __half2 h01 = __floats2half2_rn(v4.x, v4.y);
            __half2 h23 = __floats2half2_rn(v4.z, v4.w);
            uint2 st;
            st.x = *reinterpret_cast<unsigned*>(&h01);
            st.y = *reinterpret_cast<unsigned*>(&h23);
            *(uint2*)(Srow + q*4) = st;
        }
    }
    d_srp[((size_t)b*7 + (n0 >> 7))*NT + ig] = rsum;
    __syncthreads();

    float cs = 0.f;
    #pragma unroll 8
    for (int r = 0; r < 128; r++) cs += sh[r*LDE + tid];
    d_scp[((size_t)b*7 + (m0 >> 7))*NT + n0 + tid] = cs;
}

// ---------------- 3) cost (fused partial-sum reduce): fp16 S in, fp16 C + C^T out ----------------
__global__ void k_cost()
{
    int b  = blockIdx.z;
    int j0 = blockIdx.x * 32, i0 = blockIdx.y * 32;
    const __half* Sh = d_Sh + (size_t)b * NR * NR;
    __half* Ch  = d_Ch  + (size_t)b * NR * NR;
    __half* CTh = d_CTh + (size_t)b * NR * NR;
    __shared__ float tile[32][33];
    __shared__ float srv[32];
    __shared__ float scv[32];
    int tx = threadIdx.x, ty = threadIdx.y;   // (32, 8)
    int tid = ty*32 + tx;

    if (tid < 64) {
        int which = tid >> 5;    // 0: col sums, 1: row sums
        int idx   = tid & 31;
        const float* P = which ? (d_srp + (size_t)b*7*NT + i0 + idx)
                               : (d_scp + (size_t)b*7*NT + j0 + idx);
        float s = 0.f;
        #pragma unroll
        for (int t = 0; t < 7; t++) s += P[(size_t)t*NT];
        (which ? srv : scv)[idx] = s;
    }
    __syncthreads();

    int j = j0 + tx;
    float sc_j = scv[tx];
    #pragma unroll
    for (int r = 0; r < 4; r++) {
        int i = i0 + ty + 8*r;
        float s   = __half2float(Sh[(size_t)i * NR + j]);
        float den = sc_j + srv[ty + 8*r] - s;
        float c   = fmaf(-s, frcp(den), 1.0f);
        Ch[(size_t)i * NR + j] = __float2half_rn(c);
        tile[ty + 8*r][tx] = c;
    }
    __syncthreads();
    #pragma unroll
    for (int r = 0; r < 4; r++) {
        int ii = j0 + ty + 8*r;
        int jj = i0 + tx;
        CTh[(size_t)ii * NR + jj] = __float2half_rn(tile[tx][ty + 8*r]);
    }
}

// ---------------- 4) softmin: warp per row, fp16 C rows, exp2-domain ----------------
__global__ void __launch_bounds__(256) k_softmin_pair(
    const float* __restrict__ hf, const float* __restrict__ hg,
    const float* __restrict__ oldf, const float* __restrict__ oldg,
    float* __restrict__ outf, float* __restrict__ outg,
    float eps, float keps, int avg)
{
    int lane   = threadIdx.x & 31;
    int warp0  = blockIdx.x * 8 + (threadIdx.x >> 5);
    int stride = gridDim.x * 8;

    for (int gw = warp0; gw < 2*BB*NR; gw += stride) {
        int side = (gw >= BB*NR) ? 1 : 0;
        int row  = side ? gw - BB*NR : gw;
        int b    = row >> 9;
        const __half* Crow = (side ? d_CTh : d_Ch) + (size_t)row * NR;
        const float* hv   = side ? hg : hf;
        const float* oldv = side ? oldg : oldf;
        float*       ov   = side ? outg : outf;
        const float* hb   = hv ? hv + (b << 9) : nullptr;

        float a[16];
        #pragma unroll
        for (int q = 0; q < 4; q++) {
            int j = q*128 + lane*4;
            uint2 cc = *(const uint2*)(Crow + j);
            float2 c01 = __half22float2(*reinterpret_cast<__half2*>(&cc.x));
            float2 c23 = __half22float2(*reinterpret_cast<__half2*>(&cc.y));
            if (hb) {
                float4 h4 = *(const float4*)(hb + j);
                a[q*4+0] = (h4.x - c01.x) * keps;
                a[q*4+1] = (h4.y - c01.y) * keps;
                a[q*4+2] = (h4.z - c23.x) * keps;
                a[q*4+3] = (h4.w - c23.y) * keps;
            } else {
                a[q*4+0] = -c01.x * keps;
                a[q*4+1] = -c01.y * keps;
                a[q*4+2] = -c23.x * keps;
                a[q*4+3] = -c23.y * keps;
            }
        }
        float m = a[0];
        #pragma unroll
        for (int u = 1; u < 16; u++) m = fmaxf(m, a[u]);
        #pragma unroll
        for (int o = 16; o; o >>= 1) m = fmaxf(m, __shfl_xor_sync(0xffffffffu, m, o));

        float s0 = 0.f, s1 = 0.f;
        #pragma unroll
        for (int u = 0; u < 8; u++) {
            float sc0, sc1;
            float p0 = fexp2s(a[2*u]   - m, sc0);
            float p1 = fexp2s(a[2*u+1] - m, sc1);
            s0 = fmaf(p0, sc0, s0);
            s1 = fmaf(p1, sc1, s1);
        }
        float s = s0 + s1;
        #pragma unroll
        for (int o = 16; o; o >>= 1) s += __shfl_xor_sync(0xffffffffu, s, o);
        if (lane == 0) {
            float val = -eps * (fmaf(m, 0.69314718055994531f, logf(s)));
            if (avg) val = 0.5f * (oldv[row] + val);
            ov[row] = val;
        }
    }
}

// ---------------- 5) hinge GEMM: 64x64 tiles, 576 blocks (occupancy fix) ----------------
#define HSTAGE (64*LDA)        // 2304 floats
#define HINGE_SMEM (4*HSTAGE*4)  // 36864 bytes

__global__ void __launch_bounds__(128) k_hinge()
{
    extern __shared__ float sh[];
    int b  = blockIdx.z;
    int m0 = blockIdx.y * 64, n0 = blockIdx.x * 64;
    const float* Ag = d_x3r + (size_t)b * NP * DD + (size_t)m0 * DD;
    const float* Bg = d_x4r + (size_t)b * NP * DD + (size_t)n0 * DD;

    int tid = threadIdx.x;              // 128 threads, 4 warps
    int wid = tid >> 5;
    int lane = tid & 31;
    int warp_m = wid >> 1;              // 0..1
    int warp_n = wid & 1;               // 0..1

    wmma::fragment<wmma::accumulator,16,16,8,float> acc[2][2];
    #pragma unroll
    for (int mt = 0; mt < 2; mt++)
        #pragma unroll
        for (int nt = 0; nt < 2; nt++)
            wmma::fill_fragment(acc[mt][nt], 0.0f);

    int lrow = tid >> 3;                // 0..15
    int lc4  = (tid & 7) * 4;

    {
        float* A = sh; float* B = sh + HSTAGE;
        #pragma unroll
        for (int u = 0; u < 4; u++) {
            int row = lrow + 16*u;
            cp16(&A[row*LDA + lc4], Ag + (size_t)row*DD + lc4);
            cp16(&B[row*LDA + lc4], Bg + (size_t)row*DD + lc4);
        }
        asm volatile("cp.async.commit_group;");
    }

    for (int kc = 0; kc < 8; kc++) {
        if (kc < 7) {
            float* A = sh + ((kc+1)&1)*2*HSTAGE;
            float* B = A + HSTAGE;
            int k0 = (kc+1)*32;
            #pragma unroll
            for (int u = 0; u < 4; u++) {
                int row = lrow + 16*u;
                cp16(&A[row*LDA + lc4], Ag + (size_t)row*DD + k0 + lc4);
                cp16(&B[row*LDA + lc4], Bg + (size_t)row*DD + k0 + lc4);
            }
            asm volatile("cp.async.commit_group;");
            asm volatile("cp.async.wait_group 1;");
        } else {
            asm volatile("cp.async.wait_group 0;");
        }
        __syncthreads();
        const float* A = sh + (kc&1)*2*HSTAGE;
        const float* B = A + HSTAGE;
        #pragma unroll
        for (int ks = 0; ks < 4; ks++) {
            wmma::fragment<wmma::matrix_a,16,16,8,wmma::precision::tf32,wmma::row_major> af[2];
            wmma::fragment<wmma::matrix_b,16,16,8,wmma::precision::tf32,wmma::col_major> bf[2];
            #pragma unroll
            for (int mt = 0; mt < 2; mt++)
                wmma::load_matrix_sync(af[mt], &A[(warp_m*32 + mt*16)*LDA + ks*8], LDA);
            #pragma unroll
            for (int nt = 0; nt < 2; nt++)
                wmma::load_matrix_sync(bf[nt], &B[(warp_n*32 + nt*16)*LDA + ks*8], LDA);
            #pragma unroll
            for (int mt = 0; mt < 2; mt++)
                #pragma unroll
                for (int nt = 0; nt < 2; nt++)
                    wmma::mma_sync(acc[mt][nt], af[mt], bf[nt], acc[mt][nt]);
        }
        __syncthreads();
    }

    float loc = 0.f;
    #pragma unroll
    for (int mt = 0; mt < 2; mt++)
        #pragma unroll
        for (int nt = 0; nt < 2; nt++)
            #pragma unroll
            for (int e = 0; e < acc[mt][nt].num_elements; e++)
                loc += fmaxf(0.1f - acc[mt][nt].x[e], 0.0f);

    __shared__ float red[4];
    #pragma unroll
    for (int o = 16; o; o >>= 1) loc += __shfl_xor_sync(0xffffffffu, loc, o);
    if (lane == 0) red[wid] = loc;
    __syncthreads();
    if (tid == 0)
        d_hpart[b*36 + blockIdx.y*6 + blockIdx.x] =
            (red[0] + red[1]) + (red[2] + red[3]);
}

// ---------------- 6) deterministic final reduction ----------------
__global__ void k_finalize(float* __restrict__ out)
{
    int t = threadIdx.x;
    double acc = 0.0;
    for (int idx = t; idx < BB*NR; idx += 256)
        acc += (double)d_du2[idx] + (double)d_du3[idx];
    double h = 0.0;
    for (int idx = t; idx < 576; idx += 256) h += (double)d_hpart[idx];
    __shared__ double sa[256];
    __shared__ double sb[256];
    sa[t] = acc; sb[t] = h;
    __syncthreads();
    for (int o = 128; o; o >>= 1) {
        if (t < o) { sa[t] += sa[t + o]; sb[t] += sb[t + o]; }
        __syncthreads();
    }
    if (t == 0) {
        out[0] = (float)sb[0];
        out[1] = (float)(sa[0] / (double)BB);
    }
}

// ---------------- host ----------------
extern "C" void kernel_launch(void* const* d_in, const int* in_sizes, int n_in,
                              void* d_out, int out_size)
{
    const float* x1 = (const float*)d_in[0];
    const float* x2 = (const float*)d_in[1];
    const float* x3 = (const float*)d_in[2];
    const float* x4 = (const float*)d_in[3];
    float* out = (float*)d_out;

    cudaFuncSetAttribute(k_simgemm, cudaFuncAttributeMaxDynamicSharedMemorySize, SIM_SMEM);

    float *p0, *p1, *p2, *p3;
    cudaGetSymbolAddress((void**)&p0, d_du0);
    cudaGetSymbolAddress((void**)&p1, d_du1);
    cudaGetSymbolAddress((void**)&p2, d_du2);
    cudaGetSymbolAddress((void**)&p3, d_du3);

    k_normalize<<<2*BB*NT/8, 256>>>(x1, x2, x3, x4);
    k_simgemm<<<dim3(7, 7, BB), 128, SIM_SMEM>>>();
    k_cost<<<dim3(NR/32, NR/32, BB), dim3(32, 8)>>>();
    k_hinge<<<dim3(6, 6, BB), 128, HINGE_SMEM>>>();

    const float EPS[8] = {9.0f, 9.0f, 2.25f, 0.5625f, 0.140625f,
                          0.03515625f, 0.0087890625f, 0.0025f};
    const float L2E = 1.4426950408889634f;

    // 1024 blocks: 8192 warps, exactly 2 rows per warp, one fully-resident wave
    k_softmin_pair<<<1024, 256>>>(nullptr, nullptr, nullptr, nullptr,
                                  p0, p1, 9.0f, L2E/9.0f, 0);

    float *fc = p0, *gc = p1, *fa = p2, *ga = p3;
    for (int k = 0; k < 8; k++) {
        float e = EPS[k];
        k_softmin_pair<<<1024, 256>>>(gc, fc, fc, gc, fa, ga, e, L2E/e, 1);
        float* tf = fc; fc = fa; fa = tf;
        float* tg = gc; gc = ga; ga = tg;
    }
    k_softmin_pair<<<1024, 256>>>(gc, fc, nullptr, nullptr, p2, p3,
                                  0.0025f, L2E/0.0025f, 0);

    k_finalize<<<1, 256>>>(out);
}

// round 17
// speedup vs baseline: 1.8495x; 1.4024x over previous
#include <cuda_runtime.h>
#include <cuda_fp16.h>
#include <cuda_bf16.h>
#include <cstdint>
#include <mma.h>
#include <math.h>

using namespace nvcuda;

#define BB 16      // batch
#define NR 512     // real points
#define NP 384     // padding points
#define NT 896     // total points per side
#define DD 256     // feature dim

// ---------------- scratch ----------------
__device__ __nv_bfloat16 d_f1b[BB*NT*DD];   // normalized f1 (bf16)
__device__ __nv_bfloat16 d_f2b[BB*NT*DD];   // normalized f2 (bf16)
__device__ __nv_bfloat16 d_x3b[BB*NP*DD];   // raw x3 (bf16)
__device__ __nv_bfloat16 d_x4b[BB*NP*DD];   // raw x4 (bf16)
__device__ __half d_Sh [BB*NR*NR];          // S in fp16
__device__ __half d_Ch [BB*NR*NR];          // C  in fp16
__device__ __half d_CTh[BB*NR*NR];          // C^T in fp16
__device__ float  d_srp[BB*7*NT];
__device__ float  d_scp[BB*7*NT];
__device__ float  d_du0[BB*NR];
__device__ float  d_du1[BB*NR];
__device__ float  d_du2[BB*NR];
__device__ float  d_du3[BB*NR];
__device__ float  d_hpart[144];

// ---------------- FMA-only helpers ----------------
// 2^y, clamped below at -125.  Degree-4 poly in r = y - round(y)  (max rel err ~6e-5).
__device__ __forceinline__ float fexp2s(float y, float& scale) {
    y = fmaxf(y, -125.0f);
    float Y = y + 12582912.0f;
    int   n = __float_as_int(Y);
    float fi = Y - 12582912.0f;
    float r = y - fi;
    float p =           9.6181291e-3f;
    p = fmaf(p, r, 5.5504109e-2f);
    p = fmaf(p, r, 2.4022651e-1f);
    p = fmaf(p, r, 6.9314718e-1f);
    p = fmaf(p, r, 1.0f);
    scale = __int_as_float((unsigned)((n - 0x4B400000 + 127) << 23));
    return p;
}

__device__ __forceinline__ float fexp2v(float y) {
    float s;
    float p = fexp2s(y, s);
    return p * s;
}

__device__ __forceinline__ float frcp(float x) {
    float r = __int_as_float(0x7EF311C3 - __float_as_int(x));
    r = r * fmaf(-x, r, 2.0f);
    r = r * fmaf(-x, r, 2.0f);
    r = r * fmaf(-x, r, 2.0f);
    return r;
}

__device__ __forceinline__ void cp16(void* s, const void* g) {
    unsigned int sa = (unsigned int)__cvta_generic_to_shared(s);
    asm volatile("cp.async.cg.shared.global [%0], [%1], 16;" :: "r"(sa), "l"(g));
}

// ---------------- 1) normalize -> bf16; also emit bf16 raw x3/x4 ----------------
__global__ void __launch_bounds__(256) k_normalize(
    const float* __restrict__ x1, const float* __restrict__ x2,
    const float* __restrict__ x3, const float* __restrict__ x4)
{
    int gw   = blockIdx.x * 8 + (threadIdx.x >> 5);
    int lane = threadIdx.x & 31;
    int which = (gw >= BB*NT) ? 1 : 0;
    int r     = which ? gw - BB*NT : gw;
    int b = r / NT, i = r % NT;
    const float* src;
    __nv_bfloat16* rawdst = nullptr;
    if (i < NR) {
        src = (which ? x2 : x1) + ((size_t)(b*NR + i)) * DD;
    } else {
        size_t off = ((size_t)(b*NP + (i - NR))) * DD;
        src = (which ? x4 : x3) + off;
        rawdst = (which ? d_x4b : d_x3b) + off;
    }
    __nv_bfloat16* dst = (which ? d_f2b : d_f1b) + (size_t)r * DD;

    float4 v0 = *(const float4*)(src + lane*4);
    float4 v1 = *(const float4*)(src + 128 + lane*4);
    if (rawdst) {
        __nv_bfloat162 r0 = __floats2bfloat162_rn(v0.x, v0.y);
        __nv_bfloat162 r1 = __floats2bfloat162_rn(v0.z, v0.w);
        __nv_bfloat162 r2 = __floats2bfloat162_rn(v1.x, v1.y);
        __nv_bfloat162 r3 = __floats2bfloat162_rn(v1.z, v1.w);
        uint2 a, bpk;
        a.x = *reinterpret_cast<unsigned*>(&r0); a.y = *reinterpret_cast<unsigned*>(&r1);
        bpk.x = *reinterpret_cast<unsigned*>(&r2); bpk.y = *reinterpret_cast<unsigned*>(&r3);
        *(uint2*)(rawdst + lane*4)       = a;
        *(uint2*)(rawdst + 128 + lane*4) = bpk;
    }
    float sq = v0.x*v0.x + v0.y*v0.y + v0.z*v0.z + v0.w*v0.w
             + v1.x*v1.x + v1.y*v1.y + v1.z*v1.z + v1.w*v1.w;
    #pragma unroll
    for (int o = 16; o; o >>= 1) sq += __shfl_xor_sync(0xffffffffu, sq, o);
    float rn = 1.0f / fmaxf(sqrtf(sq), 1e-12f);
    v0.x *= rn; v0.y *= rn; v0.z *= rn; v0.w *= rn;
    v1.x *= rn; v1.y *= rn; v1.z *= rn; v1.w *= rn;
    {
        __nv_bfloat162 r0 = __floats2bfloat162_rn(v0.x, v0.y);
        __nv_bfloat162 r1 = __floats2bfloat162_rn(v0.z, v0.w);
        __nv_bfloat162 r2 = __floats2bfloat162_rn(v1.x, v1.y);
        __nv_bfloat162 r3 = __floats2bfloat162_rn(v1.z, v1.w);
        uint2 a, bpk;
        a.x = *reinterpret_cast<unsigned*>(&r0); a.y = *reinterpret_cast<unsigned*>(&r1);
        bpk.x = *reinterpret_cast<unsigned*>(&r2); bpk.y = *reinterpret_cast<unsigned*>(&r3);
        *(uint2*)(dst + lane*4)       = a;
        *(uint2*)(dst + 128 + lane*4) = bpk;
    }
}

// ---------------- 2) pipelined bf16 GEMM, 4 warps x (64x64 tiles), fp16 S out ----------------
#define LDH 40                 // halves; 80 B row stride -> conflict-free ldmatrix
#define LDE 132                // fp32 epilogue stride
#define STAGE_H (128*LDH)      // 5120 halves = 10240 B per matrix per stage
#define SIM_SMEM 73728         // >= max(4*STAGE_H*2 = 40960, 128*LDE*4 = 67584)
#define L2E10 14.4269504088896340736f   // 10 * log2(e)

__global__ void __launch_bounds__(128) k_simgemm()
{
    extern __shared__ float sh[];
    __nv_bfloat16* shh = reinterpret_cast<__nv_bfloat16*>(sh);

    int b  = blockIdx.z;
    int m0 = blockIdx.y * 128, n0 = blockIdx.x * 128;
    if (m0 >= NR && n0 >= NR) return;   // padding x padding feeds nothing

    const __nv_bfloat16* Ag = d_f1b + (size_t)b * NT * DD + (size_t)m0 * DD;
    const __nv_bfloat16* Bg = d_f2b + (size_t)b * NT * DD + (size_t)n0 * DD;

    int tid = threadIdx.x;              // 128 threads, 4 warps
    int wid = tid >> 5;
    int warp_m = wid >> 1;              // 0..1
    int warp_n = wid & 1;               // 0..1

    wmma::fragment<wmma::accumulator,16,16,16,float> acc[4][4];
    #pragma unroll
    for (int mt = 0; mt < 4; mt++)
        #pragma unroll
        for (int nt = 0; nt < 4; nt++)
            wmma::fill_fragment(acc[mt][nt], 0.0f);

    int lrow = tid >> 2;                // 0..31
    int lch  = (tid & 3) * 8;           // half offset within 32-half chunk

    {
        __nv_bfloat16* A = shh; __nv_bfloat16* B = shh + STAGE_H;
        #pragma unroll
        for (int u = 0; u < 4; u++) {
            int row = lrow + 32*u;
            cp16(&A[row*LDH + lch], Ag + (size_t)row*DD + lch);
            cp16(&B[row*LDH + lch], Bg + (size_t)row*DD + lch);
        }
        asm volatile("cp.async.commit_group;");
    }

    for (int kc = 0; kc < 8; kc++) {
        if (kc < 7) {
            __nv_bfloat16* A = shh + ((kc+1)&1)*2*STAGE_H;
            __nv_bfloat16* B = A + STAGE_H;
            int k0 = (kc+1)*32;
            #pragma unroll
            for (int u = 0; u < 4; u++) {
                int row = lrow + 32*u;
                cp16(&A[row*LDH + lch], Ag + (size_t)row*DD + k0 + lch);
                cp16(&B[row*LDH + lch], Bg + (size_t)row*DD + k0 + lch);
            }
            asm volatile("cp.async.commit_group;");
            asm volatile("cp.async.wait_group 1;");
        } else {
            asm volatile("cp.async.wait_group 0;");
        }
        __syncthreads();
        const __nv_bfloat16* A = shh + (kc&1)*2*STAGE_H;
        const __nv_bfloat16* B = A + STAGE_H;
        #pragma unroll
        for (int ks = 0; ks < 2; ks++) {
            wmma::fragment<wmma::matrix_a,16,16,16,__nv_bfloat16,wmma::row_major> af[4];
            wmma::fragment<wmma::matrix_b,16,16,16,__nv_bfloat16,wmma::col_major> bf[4];
            #pragma unroll
            for (int mt = 0; mt < 4; mt++)
                wmma::load_matrix_sync(af[mt], &A[(warp_m*64 + mt*16)*LDH + ks*16], LDH);
            #pragma unroll
            for (int nt = 0; nt < 4; nt++)
                wmma::load_matrix_sync(bf[nt], &B[(warp_n*64 + nt*16)*LDH + ks*16], LDH);
            #pragma unroll
            for (int mt = 0; mt < 4; mt++)
                #pragma unroll
                for (int nt = 0; nt < 4; nt++)
                    wmma::mma_sync(acc[mt][nt], af[mt], bf[nt], acc[mt][nt]);
        }
        __syncthreads();
    }

    // epilogue: store acc to sh[128][LDE] fp32, thread-per-row exp + sums, fp16 store
    #pragma unroll
    for (int mt = 0; mt < 4; mt++)
        #pragma unroll
        for (int nt = 0; nt < 4; nt++)
            wmma::store_matrix_sync(&sh[(warp_m*64 + mt*16)*LDE + warp_n*64 + nt*16],
                                    acc[mt][nt], LDE, wmma::mem_row_major);
    __syncthreads();

    bool inblk = (m0 < NR) && (n0 < NR);
    int ig = m0 + tid;
    float rsum = 0.f;
    __half* Srow = d_Sh + ((size_t)b*NR + ig)*NR + n0;
    #pragma unroll
    for (int q = 0; q < 32; q++) {
        float4 v4 = *(float4*)&sh[tid*LDE + q*4];
        v4.x = fexp2v(L2E10 * v4.x);
        v4.y = fexp2v(L2E10 * v4.y);
        v4.z = fexp2v(L2E10 * v4.z);
        v4.w = fexp2v(L2E10 * v4.w);
        rsum += (v4.x + v4.y) + (v4.z + v4.w);
        *(float4*)&sh[tid*LDE + q*4] = v4;
        if (inblk) {
            __half2 h01 = __floats2half2_rn(v4.x, v4.y);
            __half2 h23 = __floats2half2_rn(v4.z, v4.w);
            uint2 st;
            st.x = *reinterpret_cast<unsigned*>(&h01);
            st.y = *reinterpret_cast<unsigned*>(&h23);
            *(uint2*)(Srow + q*4) = st;
        }
    }
    d_srp[((size_t)b*7 + (n0 >> 7))*NT + ig] = rsum;
    __syncthreads();

    float cs = 0.f;
    #pragma unroll 8
    for (int r = 0; r < 128; r++) cs += sh[r*LDE + tid];
    d_scp[((size_t)b*7 + (m0 >> 7))*NT + n0 + tid] = cs;
}

// ---------------- 3) cost (fused partial-sum reduce): fp16 S in, fp16 C + C^T out ----------------
__global__ void k_cost()
{
    int b  = blockIdx.z;
    int j0 = blockIdx.x * 32, i0 = blockIdx.y * 32;
    const __half* Sh = d_Sh + (size_t)b * NR * NR;
    __half* Ch  = d_Ch  + (size_t)b * NR * NR;
    __half* CTh = d_CTh + (size_t)b * NR * NR;
    __shared__ float tile[32][33];
    __shared__ float srv[32];
    __shared__ float scv[32];
    int tx = threadIdx.x, ty = threadIdx.y;   // (32, 8)
    int tid = ty*32 + tx;

    if (tid < 64) {
        int which = tid >> 5;    // 0: col sums, 1: row sums
        int idx   = tid & 31;
        const float* P = which ? (d_srp + (size_t)b*7*NT + i0 + idx)
                               : (d_scp + (size_t)b*7*NT + j0 + idx);
        float s = 0.f;
        #pragma unroll
        for (int t = 0; t < 7; t++) s += P[(size_t)t*NT];
        (which ? srv : scv)[idx] = s;
    }
    __syncthreads();

    int j = j0 + tx;
    float sc_j = scv[tx];
    #pragma unroll
    for (int r = 0; r < 4; r++) {
        int i = i0 + ty + 8*r;
        float s   = __half2float(Sh[(size_t)i * NR + j]);
        float den = sc_j + srv[ty + 8*r] - s;
        float c   = fmaf(-s, frcp(den), 1.0f);
        Ch[(size_t)i * NR + j] = __float2half_rn(c);
        tile[ty + 8*r][tx] = c;
    }
    __syncthreads();
    #pragma unroll
    for (int r = 0; r < 4; r++) {
        int ii = j0 + ty + 8*r;
        int jj = i0 + tx;
        CTh[(size_t)ii * NR + jj] = __float2half_rn(tile[tx][ty + 8*r]);
    }
}

// ---------------- 4) softmin: warp per row, fp16 C rows, exp2-domain ----------------
__global__ void __launch_bounds__(256) k_softmin_pair(
    const float* __restrict__ hf, const float* __restrict__ hg,
    const float* __restrict__ oldf, const float* __restrict__ oldg,
    float* __restrict__ outf, float* __restrict__ outg,
    float eps, float keps, int avg)
{
    int lane   = threadIdx.x & 31;
    int warp0  = blockIdx.x * 8 + (threadIdx.x >> 5);
    int stride = gridDim.x * 8;

    for (int gw = warp0; gw < 2*BB*NR; gw += stride) {
        int side = (gw >= BB*NR) ? 1 : 0;
        int row  = side ? gw - BB*NR : gw;
        int b    = row >> 9;
        const __half* Crow = (side ? d_CTh : d_Ch) + (size_t)row * NR;
        const float* hv   = side ? hg : hf;
        const float* oldv = side ? oldg : oldf;
        float*       ov   = side ? outg : outf;
        const float* hb   = hv ? hv + (b << 9) : nullptr;

        float a[16];
        #pragma unroll
        for (int q = 0; q < 4; q++) {
            int j = q*128 + lane*4;
            uint2 cc = *(const uint2*)(Crow + j);
            float2 c01 = __half22float2(*reinterpret_cast<__half2*>(&cc.x));
            float2 c23 = __half22float2(*reinterpret_cast<__half2*>(&cc.y));
            if (hb) {
                float4 h4 = *(const float4*)(hb + j);
                a[q*4+0] = (h4.x - c01.x) * keps;
                a[q*4+1] = (h4.y - c01.y) * keps;
                a[q*4+2] = (h4.z - c23.x) * keps;
                a[q*4+3] = (h4.w - c23.y) * keps;
            } else {
                a[q*4+0] = -c01.x * keps;
                a[q*4+1] = -c01.y * keps;
                a[q*4+2] = -c23.x * keps;
                a[q*4+3] = -c23.y * keps;
            }
        }
        float m = a[0];
        #pragma unroll
        for (int u = 1; u < 16; u++) m = fmaxf(m, a[u]);
        #pragma unroll
        for (int o = 16; o; o >>= 1) m = fmaxf(m, __shfl_xor_sync(0xffffffffu, m, o));

        float s0 = 0.f, s1 = 0.f;
        #pragma unroll
        for (int u = 0; u < 8; u++) {
            float sc0, sc1;
            float p0 = fexp2s(a[2*u]   - m, sc0);
            float p1 = fexp2s(a[2*u+1] - m, sc1);
            s0 = fmaf(p0, sc0, s0);
            s1 = fmaf(p1, sc1, s1);
        }
        float s = s0 + s1;
        #pragma unroll
        for (int o = 16; o; o >>= 1) s += __shfl_xor_sync(0xffffffffu, s, o);
        if (lane == 0) {
            float val = -eps * (fmaf(m, 0.69314718055994531f, logf(s)));
            if (avg) val = 0.5f * (oldv[row] + val);
            ov[row] = val;
        }
    }
}

// ---------------- 5) hinge GEMM (bf16, 128x128 tile, 4 warps x 64x64) ----------------
__global__ void __launch_bounds__(128) k_hinge()
{
    extern __shared__ float sh[];
    __nv_bfloat16* shh = reinterpret_cast<__nv_bfloat16*>(sh);

    int b  = blockIdx.z;
    int m0 = blockIdx.y * 128, n0 = blockIdx.x * 128;
    const __nv_bfloat16* Ag = d_x3b + (size_t)b * NP * DD + (size_t)m0 * DD;
    const __nv_bfloat16* Bg = d_x4b + (size_t)b * NP * DD + (size_t)n0 * DD;

    int tid = threadIdx.x;
    int wid = tid >> 5;
    int lane = tid & 31;
    int warp_m = wid >> 1;
    int warp_n = wid & 1;

    wmma::fragment<wmma::accumulator,16,16,16,float> acc[4][4];
    #pragma unroll
    for (int mt = 0; mt < 4; mt++)
        #pragma unroll
        for (int nt = 0; nt < 4; nt++)
            wmma::fill_fragment(acc[mt][nt], 0.0f);

    int lrow = tid >> 2;
    int lch  = (tid & 3) * 8;

    {
        __nv_bfloat16* A = shh; __nv_bfloat16* B = shh + STAGE_H;
        #pragma unroll
        for (int u = 0; u < 4; u++) {
            int row = lrow + 32*u;
            cp16(&A[row*LDH + lch], Ag + (size_t)row*DD + lch);
            cp16(&B[row*LDH + lch], Bg + (size_t)row*DD + lch);
        }
        asm volatile("cp.async.commit_group;");
    }

    for (int kc = 0; kc < 8; kc++) {
        if (kc < 7) {
            __nv_bfloat16* A = shh + ((kc+1)&1)*2*STAGE_H;
            __nv_bfloat16* B = A + STAGE_H;
            int k0 = (kc+1)*32;
            #pragma unroll
            for (int u = 0; u < 4; u++) {
                int row = lrow + 32*u;
                cp16(&A[row*LDH + lch], Ag + (size_t)row*DD + k0 + lch);
                cp16(&B[row*LDH + lch], Bg + (size_t)row*DD + k0 + lch);
            }
            asm volatile("cp.async.commit_group;");
            asm volatile("cp.async.wait_group 1;");
        } else {
            asm volatile("cp.async.wait_group 0;");
        }
        __syncthreads();
        const __nv_bfloat16* A = shh + (kc&1)*2*STAGE_H;
        const __nv_bfloat16* B = A + STAGE_H;
        #pragma unroll
        for (int ks = 0; ks < 2; ks++) {
            wmma::fragment<wmma::matrix_a,16,16,16,__nv_bfloat16,wmma::row_major> af[4];
            wmma::fragment<wmma::matrix_b,16,16,16,__nv_bfloat16,wmma::col_major> bf[4];
            #pragma unroll
            for (int mt = 0; mt < 4; mt++)
                wmma::load_matrix_sync(af[mt], &A[(warp_m*64 + mt*16)*LDH + ks*16], LDH);
            #pragma unroll
            for (int nt = 0; nt < 4; nt++)
                wmma::load_matrix_sync(bf[nt], &B[(warp_n*64 + nt*16)*LDH + ks*16], LDH);
            #pragma unroll
            for (int mt = 0; mt < 4; mt++)
                #pragma unroll
                for (int nt = 0; nt < 4; nt++)
                    wmma::mma_sync(acc[mt][nt], af[mt], bf[nt], acc[mt][nt]);
        }
        __syncthreads();
    }

    float loc = 0.f;
    #pragma unroll
    for (int mt = 0; mt < 4; mt++)
        #pragma unroll
        for (int nt = 0; nt < 4; nt++)
            #pragma unroll
            for (int e = 0; e < acc[mt][nt].num_elements; e++)
                loc += fmaxf(0.1f - acc[mt][nt].x[e], 0.0f);

    __shared__ float red[4];
    #pragma unroll
    for (int o = 16; o; o >>= 1) loc += __shfl_xor_sync(0xffffffffu, loc, o);
    if (lane == 0) red[wid] = loc;
    __syncthreads();
    if (tid == 0)
        d_hpart[b*9 + blockIdx.y*3 + blockIdx.x] =
            (red[0] + red[1]) + (red[2] + red[3]);
}

// ---------------- 6) deterministic final reduction ----------------
__global__ void k_finalize(float* __restrict__ out)
{
    int t = threadIdx.x;
    double acc = 0.0;
    for (int idx = t; idx < BB*NR; idx += 256)
        acc += (double)d_du2[idx] + (double)d_du3[idx];
    double h = 0.0;
    for (int idx = t; idx < 144; idx += 256) h += (double)d_hpart[idx];
    __shared__ double sa[256];
    __shared__ double sb[256];
    sa[t] = acc; sb[t] = h;
    __syncthreads();
    for (int o = 128; o; o >>= 1) {
        if (t < o) { sa[t] += sa[t + o]; sb[t] += sb[t + o]; }
        __syncthreads();
    }
    if (t == 0) {
        out[0] = (float)sb[0];
        out[1] = (float)(sa[0] / (double)BB);
    }
}

// ---------------- host ----------------
extern "C" void kernel_launch(void* const* d_in, const int* in_sizes, int n_in,
                              void* d_out, int out_size)
{
    const float* x1 = (const float*)d_in[0];
    const float* x2 = (const float*)d_in[1];
    const float* x3 = (const float*)d_in[2];
    const float* x4 = (const float*)d_in[3];
    float* out = (float*)d_out;

    cudaFuncSetAttribute(k_simgemm, cudaFuncAttributeMaxDynamicSharedMemorySize, SIM_SMEM);
    cudaFuncSetAttribute(k_hinge,   cudaFuncAttributeMaxDynamicSharedMemorySize, SIM_SMEM);

    float *p0, *p1, *p2, *p3;
    cudaGetSymbolAddress((void**)&p0, d_du0);
    cudaGetSymbolAddress((void**)&p1, d_du1);
    cudaGetSymbolAddress((void**)&p2, d_du2);
    cudaGetSymbolAddress((void**)&p3, d_du3);

    k_normalize<<<2*BB*NT/8, 256>>>(x1, x2, x3, x4);
    k_simgemm<<<dim3(7, 7, BB), 128, SIM_SMEM>>>();
    k_cost<<<dim3(NR/32, NR/32, BB), dim3(32, 8)>>>();
    k_hinge<<<dim3(3, 3, BB), 128, SIM_SMEM>>>();

    const float EPS[8] = {9.0f, 9.0f, 2.25f, 0.5625f, 0.140625f,
                          0.03515625f, 0.0087890625f, 0.0025f};
    const float L2E = 1.4426950408889634f;

    // 1024 blocks: 8192 warps, exactly 2 rows per warp, one fully-resident wave
    k_softmin_pair<<<1024, 256>>>(nullptr, nullptr, nullptr, nullptr,
                                  p0, p1, 9.0f, L2E/9.0f, 0);

    float *fc = p0, *gc = p1, *fa = p2, *ga = p3;
    for (int k = 0; k < 8; k++) {
        float e = EPS[k];
        k_softmin_pair<<<1024, 256>>>(gc, fc, fc, gc, fa, ga, e, L2E/e, 1);
        float* tf = fc; fc = fa; fa = tf;
        float* tg = gc; gc = ga; ga = tg;
    }
    k_softmin_pair<<<1024, 256>>>(gc, fc, nullptr, nullptr, p2, p3,
                                  0.0025f, L2E/0.0025f, 0);

    k_finalize<<<1, 256>>>(out);
}